// round 10
// baseline (speedup 1.0000x reference)
#include <cuda_runtime.h>
#include <cstdint>

// Problem constants
#define BATCH 16
#define NA    3
#define NC    20
#define NATTR 25          // 5 + NC
#define IH    52
#define IW    52
#define HW    2704        // IH*IW
#define NBOX  8112        // NA*HW
#define NPAD  8192
#define TOPK  2048
#define NWORDS (TOPK / 64)    // 32 u64 words per suppression row
#define NBLK   (TOPK / 64)    // 32 blocks of 64 candidates
#define STRIDE_F 8.0f

typedef unsigned long long u64;

// Accurate libdevice expf (XLA's f32 exp lowering), immune to --use_fast_math.
extern "C" __device__ float __nv_expf(float);

// Scratch (allocation-free: __device__ globals)
__device__ float g_conf[BATCH][NBOX];
__device__ int   g_cls [BATCH][NBOX];
__device__ u64   g_runA[BATCH][NPAD];
__device__ u64   g_runB[BATCH][NPAD];

// NMS staging
__device__ float g_x1[BATCH][TOPK];
__device__ float g_y1[BATCH][TOPK];
__device__ float g_x2[BATCH][TOPK];
__device__ float g_y2[BATCH][TOPK];
__device__ float g_ar[BATCH][TOPK];
__device__ short g_cl[BATCH][TOPK];
__device__ u64   g_vab[BATCH][NWORDS];          // validity bitmask
__device__ u64   g_mask[BATCH][TOPK][NWORDS];   // 8 MB suppression matrix

// ---------------------------------------------------------------------------
// Bitwise replica of XLA:GPU's tanh (llvm_ir::EmitFastTanh).
// ---------------------------------------------------------------------------
__device__ __forceinline__ float xla_tanhf(float x) {
    float ax = fabsf(x);
    float xc = fminf(fmaxf(x, -7.90531110763549805f), 7.90531110763549805f);
    float x2 = __fmul_rn(xc, xc);
    float p = -2.76076847742355e-16f;
    p = __fmaf_rn(x2, p, 2.00018790482477e-13f);
    p = __fmaf_rn(x2, p, -8.60467152213735e-11f);
    p = __fmaf_rn(x2, p, 5.12229709037114e-08f);
    p = __fmaf_rn(x2, p, 1.48572235717979e-05f);
    p = __fmaf_rn(x2, p, 6.37261928875436e-04f);
    p = __fmaf_rn(x2, p, 4.89352455891786e-03f);
    p = __fmul_rn(xc, p);
    float q = 1.19825839466702e-06f;
    q = __fmaf_rn(x2, q, 1.18534705686654e-04f);
    q = __fmaf_rn(x2, q, 2.26843463243900e-03f);
    q = __fmaf_rn(x2, q, 4.89352518554385e-03f);
    float r = __fdiv_rn(p, q);
    return (ax < 0.0004f) ? x : r;
}

__device__ __forceinline__ float sigmoid_xla(float x) {
    float t = xla_tanhf(__fmul_rn(0.5f, x));
    return __fmaf_rn(0.5f, t, 0.5f);
}

// ---------------------------------------------------------------------------
// Kernel 1: decode (identical math — measured ~20us).
// ---------------------------------------------------------------------------
__global__ void decode_kernel(const float* __restrict__ in,
                              const float* __restrict__ anchors,
                              float* __restrict__ out) {
    __shared__ float s_out[256 * NATTR];

    int t = blockIdx.x * 256 + threadIdx.x;     // grid sized exactly: no tail
    int b = t / NBOX, n = t % NBOX;
    int a = n / HW,   r = n % HW;
    int gy = r / IW,  gx = r % IW;

    const float* base = in + ((size_t)(b * NA + a) * NATTR) * HW + r;
    float t0 = base[0 * HW];
    float t1 = base[1 * HW];
    float t2 = base[2 * HW];
    float t3 = base[3 * HW];
    float t4 = base[4 * HW];

    float aw = __fdiv_rn(anchors[a * 2 + 0], STRIDE_F);
    float ah = __fdiv_rn(anchors[a * 2 + 1], STRIDE_F);

    float sx = sigmoid_xla(t0);
    float sy = sigmoid_xla(t1);
    float bx = __fmul_rn(__fadd_rn(sx, (float)gx), STRIDE_F);
    float by = __fmul_rn(__fadd_rn(sy, (float)gy), STRIDE_F);
    float bw = __fmul_rn(__fmul_rn(__nv_expf(t2), aw), STRIDE_F);
    float bh = __fmul_rn(__fmul_rn(__nv_expf(t3), ah), STRIDE_F);
    float conf = sigmoid_xla(t4);

    float* so = s_out + threadIdx.x * NATTR;
    so[0] = bx; so[1] = by; so[2] = bw; so[3] = bh; so[4] = conf;

    float bestv = -3.402823466e+38f;
    int best = 0;
#pragma unroll
    for (int c = 0; c < NC; c++) {
        float v = sigmoid_xla(base[(5 + c) * HW]);
        so[5 + c] = v;
        if (v > bestv) { bestv = v; best = c; }
    }
    g_conf[b][n] = conf;
    g_cls[b][n]  = best;
    __syncthreads();

    float* oblk = out + (size_t)blockIdx.x * 256 * NATTR;
    for (int k = threadIdx.x; k < 256 * NATTR; k += 256)
        oblk[k] = s_out[k];
}

// ---------------------------------------------------------------------------
// Top-K: truncated tournament merge. key = (conf_bits<<32)|(~idx);
// desc = conf desc then idx asc. Run r sorted DESC iff popcount(r) even.
// ---------------------------------------------------------------------------
__device__ __forceinline__ u64 cex(u64 a, u64 v, bool lower, bool desc) {
    u64 mx = a > v ? a : v;
    u64 mn = a > v ? v : a;
    return desc ? (lower ? mx : mn) : (lower ? mn : mx);
}

// 2a: local sort of 8 x 1024 runs per batch; element register-resident.
__global__ void local_sort(void) {
    __shared__ u64 s[1024];
    int c = blockIdx.x, b = blockIdx.y, t = threadIdx.x;
    int i = c * 1024 + t;
    u64 mine = 0ull;
    if (i < NBOX) {
        unsigned cb = __float_as_uint(g_conf[b][i]);
        mine = ((u64)cb << 32) | (unsigned)(0xFFFFFFFFu - (unsigned)i);
    }
    bool dirDesc = ((__popc(c) & 1) == 0);

    for (int k2 = 2; k2 <= 1024; k2 <<= 1) {
        for (int j = k2 >> 1; j > 0; j >>= 1) {
            bool descb = (((t & k2) == 0) == dirDesc);
            bool lower = (t & j) == 0;
            if (j >= 32) {
                s[t] = mine;
                __syncthreads();
                u64 v = s[t ^ j];
                mine = cex(mine, v, lower, descb);
                __syncthreads();
            } else {
                u64 v = __shfl_xor_sync(0xFFFFFFFFu, mine, j);
                mine = cex(mine, v, lower, descb);
            }
        }
    }
    g_runA[b][c * 1024 + t] = mine;
}

// Descending/ascending bitonic merge of a 2048-element bitonic sequence held
// as (r0 = elem t, r1 = elem t+1024). j=1024 in-register; 512..32 smem; 16..1 shfl.
__device__ __forceinline__ void bitonic_merge_2048(u64& r0, u64& r1,
                                                   u64* s, int t, bool dirDesc) {
    {   // j = 1024: in-thread pair, r0 is lower
        bool sw = dirDesc ? (r0 < r1) : (r0 > r1);
        if (sw) { u64 tmp = r0; r0 = r1; r1 = tmp; }
    }
#pragma unroll
    for (int j = 512; j >= 32; j >>= 1) {
        s[t] = r0; s[t + 1024] = r1;
        __syncthreads();
        u64 v0 = s[t ^ j];
        u64 v1 = s[(t ^ j) + 1024];
        bool lower = (t & j) == 0;
        r0 = cex(r0, v0, lower, dirDesc);
        r1 = cex(r1, v1, lower, dirDesc);
        __syncthreads();
    }
#pragma unroll
    for (int j = 16; j >= 1; j >>= 1) {
        u64 v0 = __shfl_xor_sync(0xFFFFFFFFu, r0, j);
        u64 v1 = __shfl_xor_sync(0xFFFFFFFFu, r1, j);
        bool lower = (t & j) == 0;
        r0 = cex(r0, v0, lower, dirDesc);
        r1 = cex(r1, v1, lower, dirDesc);
    }
}

// 2b: merge pass. RUNLEN=1024: full merge 2x1024 -> 2048.
//     RUNLEN=2048: truncating merge 2x2048 -> top 2048 (bitonic split).
template<int RUNLEN, int SRCA>
__global__ void merge_pass(void) {
    __shared__ u64 s[2048];
    int m = blockIdx.x, b = blockIdx.y, t = threadIdx.x;
    const u64* in = SRCA ? g_runA[b] : g_runB[b];
    u64* outp     = SRCA ? g_runB[b] : g_runA[b];
    const u64* A  = in + 2 * m * RUNLEN;
    const u64* Bp = A + RUNLEN;
    bool dirDesc = ((__popc(m) & 1) == 0);

    u64 r0, r1;
    if (RUNLEN == 1024) {
        r0 = A[t];                 // element t
        r1 = Bp[t];                // element t+1024
    } else {
        u64 a0 = A[t],        b0 = Bp[t];
        u64 a1 = A[t + 1024], b1 = Bp[t + 1024];
        r0 = a0 > b0 ? a0 : b0;    // bitonic split: top half
        r1 = a1 > b1 ? a1 : b1;
    }
    bitonic_merge_2048(r0, r1, s, t, dirDesc);
    outp[m * 2048 + t]        = r0;
    outp[m * 2048 + 1024 + t] = r1;
}

// 2c: final truncating merge (desc) + fused NMS prep. grid (BATCH), 1024 thr.
__global__ void merge_final(const float* __restrict__ out,
                            float* __restrict__ out_topidx) {
    __shared__ u64 s[2048];
    __shared__ unsigned s_vab32[64];
    int b = blockIdx.x, t = threadIdx.x;
    if (t < 64) s_vab32[t] = 0u;

    const u64* A  = g_runA[b];
    const u64* Bp = A + 2048;
    u64 a0 = A[t],        b0 = Bp[t];
    u64 a1 = A[t + 1024], b1 = Bp[t + 1024];
    u64 r0 = a0 > b0 ? a0 : b0;
    u64 r1 = a1 > b1 ? a1 : b1;
    bitonic_merge_2048(r0, r1, s, t, true);

#pragma unroll
    for (int q = 0; q < 2; q++) {
        int i = t + q * 1024;
        u64 kk = q ? r1 : r0;
        int n = (int)(0xFFFFFFFFu - (unsigned)(kk & 0xFFFFFFFFull));
        out_topidx[b * TOPK + i] = (float)n;

        const float* o = out + ((size_t)b * NBOX + n) * NATTR;
        float cx = o[0], cy = o[1], w = o[2], h = o[3];
        float conf = __uint_as_float((unsigned)(kk >> 32));
        float hw2 = __fmul_rn(w, 0.5f);
        float hh2 = __fmul_rn(h, 0.5f);
        float x1 = __fsub_rn(cx, hw2);
        float y1 = __fsub_rn(cy, hh2);
        float x2 = __fadd_rn(cx, hw2);
        float y2 = __fadd_rn(cy, hh2);
        g_x1[b][i] = x1; g_y1[b][i] = y1; g_x2[b][i] = x2; g_y2[b][i] = y2;
        g_ar[b][i] = __fmul_rn(__fadd_rn(__fsub_rn(x2, x1), 1.0f),
                               __fadd_rn(__fsub_rn(y2, y1), 1.0f));
        g_cl[b][i] = (short)g_cls[b][n];
        if (conf >= 0.5f)
            atomicOr(&s_vab32[i >> 5], 1u << (i & 31));
    }
    __syncthreads();
    if (t < 64) ((unsigned*)g_vab[b])[t] = s_vab32[t];
}

// ---------------------------------------------------------------------------
// Kernel 3: suppression mask — one CTA per (row-block ib, batch). i-boxes in
// registers once; loop over j-blocks >= ib staged in smem. Same bits as the
// measured-passing version.
// ---------------------------------------------------------------------------
__global__ void nms_mask(void) {
    int ib = blockIdx.x, b = blockIdx.y;
    int t = threadIdx.x;                    // 64 threads

    __shared__ float jx1[64], jy1[64], jx2[64], jy2[64], jar[64];
    __shared__ short jcl[64];
    __shared__ u64 s_cm[NC];

    int i = ib * 64 + t;
    float xi1 = g_x1[b][i], yi1 = g_y1[b][i];
    float xi2 = g_x2[b][i], yi2 = g_y2[b][i];
    float ai  = g_ar[b][i];
    short ci  = g_cl[b][i];

    for (int jb = ib; jb < NBLK; jb++) {
        int j0 = jb * 64;
        if (t < NC) s_cm[t] = 0ull;
        __syncthreads();
        jx1[t] = g_x1[b][j0 + t];
        jy1[t] = g_y1[b][j0 + t];
        jx2[t] = g_x2[b][j0 + t];
        jy2[t] = g_y2[b][j0 + t];
        jar[t] = g_ar[b][j0 + t];
        jcl[t] = g_cl[b][j0 + t];
        atomicOr(&s_cm[jcl[t]], 1ull << t);
        __syncthreads();

        u64 mm = s_cm[ci];
        if (jb == ib) mm = (t < 63) ? (mm & (~0ull << (t + 1))) : 0ull;

        u64 bits = 0ull;
        while (mm) {
            int jj = __ffsll((long long)mm) - 1;
            mm &= mm - 1;
            float ix1 = fmaxf(xi1, jx1[jj]);
            float iy1 = fmaxf(yi1, jy1[jj]);
            float ix2 = fminf(xi2, jx2[jj]);
            float iy2 = fminf(yi2, jy2[jj]);
            float iw = __fadd_rn(__fsub_rn(ix2, ix1), 1.0f); iw = fmaxf(iw, 0.0f);
            float ih = __fadd_rn(__fsub_rn(iy2, iy1), 1.0f); ih = fmaxf(ih, 0.0f);
            float inter = __fmul_rn(iw, ih);
            float den = __fadd_rn(__fsub_rn(__fadd_rn(ai, jar[jj]), inter), 1e-16f);
            float iou = __fdiv_rn(inter, den);
            if (iou >= 0.4f) bits |= 1ull << jj;
        }
        g_mask[b][i][jb] = bits;
        __syncthreads();
    }
}

// ---------------------------------------------------------------------------
// Kernel 4: block-greedy reduce, parallel-fetch apply. Diagonal words
// preloaded (16 KB); after resolve, thread (slot, w) fetches the slot-th KEPT
// row's word w directly from L2 — all fetches independent, one L2 round-trip
// per block. Greedy semantics identical to the validated chain.
// ---------------------------------------------------------------------------
__device__ __forceinline__ int nth_bit64(u64 x, int n) {
    unsigned lo = (unsigned)x;
    int cl = __popc(lo);
    if (n < cl) return (int)__fns(lo, 0, n + 1);
    return 32 + (int)__fns((unsigned)(x >> 32), 0, n - cl + 1);
}

__global__ void nms_reduce(float* __restrict__ keep_out) {
    __shared__ u64 diagAll[NBLK][64];       // 16 KB
    __shared__ unsigned rem32[64];
    __shared__ u64 s_vab[NWORDS];
    __shared__ u64 s_keep;

    int b = blockIdx.x, t = threadIdx.x;    // 512 threads
    if (t < 64) rem32[t] = 0u;
    if (t < NWORDS) s_vab[t] = g_vab[b][t];

    for (int k = t; k < NBLK * 64; k += 512) {
        int bk = k >> 6, u = k & 63;
        diagAll[bk][u] = g_mask[b][bk * 64 + u][bk];
    }
    __syncthreads();

    int w = t & 31, slot = t >> 5;          // 32 words x 16 slots

    for (int bk = 0; bk < NBLK; bk++) {
        // serial greedy resolve of this 64-candidate word (validated R6-R9)
        if (t == 0) {
            u64 rem = ((u64)rem32[2 * bk + 1] << 32) | rem32[2 * bk];
            u64 cand = s_vab[bk] & ~rem;
            u64 k64 = 0ull;
            while (cand) {
                int u = __ffsll((long long)cand) - 1;
                k64 |= 1ull << u;
                cand &= ~(1ull << u);
                cand &= ~diagAll[bk][u];    // bits only for j > u
            }
            s_keep = k64;
        }
        __syncthreads();
        u64 k64 = s_keep;

        if (t < 64)
            keep_out[b * TOPK + bk * 64 + t] =
                ((k64 >> t) & 1ull) ? 1.0f : 0.0f;

        // parallel apply: thread (slot, w) fetches word w of the slot-th kept
        // row; all fetches independent -> one L2 latency per block.
        int nk = __popcll(k64);
        if (w > bk && slot < nk) {
            u64 part = 0ull;
            for (int g = slot; g < nk; g += 16) {
                int u = nth_bit64(k64, g);
                part |= g_mask[b][bk * 64 + u][w];
            }
            if (part) {
                unsigned lo = (unsigned)part, hi = (unsigned)(part >> 32);
                if (lo) atomicOr(&rem32[2 * w],     lo);
                if (hi) atomicOr(&rem32[2 * w + 1], hi);
            }
        }
        __syncthreads();
    }
}

// ---------------------------------------------------------------------------
// Launch: out = [output(B*NBOX*NATTR) | top_idx(B*TOPK) | keep(B*TOPK)] float32
// ---------------------------------------------------------------------------
extern "C" void kernel_launch(void* const* d_in, const int* in_sizes, int n_in,
                              void* d_out, int out_size) {
    (void)in_sizes; (void)n_in; (void)out_size;
    const float* in      = (const float*)d_in[0];
    const float* anchors = (const float*)d_in[1];
    float* out      = (float*)d_out;
    float* top_out  = out + (size_t)BATCH * NBOX * NATTR;
    float* keep_out = top_out + (size_t)BATCH * TOPK;

    int total = BATCH * NBOX;                 // 129792 = 256 * 507, no tail
    decode_kernel<<<total / 256, 256>>>(in, anchors, out);

    local_sort<<<dim3(8, BATCH), 1024>>>();
    merge_pass<1024, 1><<<dim3(4, BATCH), 1024>>>();   // A -> B (full merges)
    merge_pass<2048, 0><<<dim3(2, BATCH), 1024>>>();   // B -> A (truncating)
    merge_final<<<BATCH, 1024>>>(out, top_out);        // A -> outputs + prep

    nms_mask<<<dim3(NBLK, BATCH), 64>>>();
    nms_reduce<<<BATCH, 512>>>(keep_out);
}

// round 11
// speedup vs baseline: 1.2299x; 1.2299x over previous
#include <cuda_runtime.h>
#include <cstdint>

// Problem constants
#define BATCH 16
#define NA    3
#define NC    20
#define NATTR 25          // 5 + NC
#define IH    52
#define IW    52
#define HW    2704        // IH*IW
#define NBOX  8112        // NA*HW
#define NPAD  8192
#define TOPK  2048
#define NWORDS (TOPK / 64)    // 32 u64 words per suppression row
#define NBLK   (TOPK / 64)    // 32 blocks of 64 candidates
#define STRIDE_F 8.0f

typedef unsigned long long u64;

// Accurate libdevice expf (XLA's f32 exp lowering), immune to --use_fast_math.
extern "C" __device__ float __nv_expf(float);

// Scratch (allocation-free: __device__ globals)
__device__ float g_conf[BATCH][NBOX];
__device__ int   g_cls [BATCH][NBOX];
__device__ u64   g_runA[BATCH][NPAD];
__device__ u64   g_runB[BATCH][NPAD];

// NMS staging
__device__ float g_x1[BATCH][TOPK];
__device__ float g_y1[BATCH][TOPK];
__device__ float g_x2[BATCH][TOPK];
__device__ float g_y2[BATCH][TOPK];
__device__ float g_ar[BATCH][TOPK];
__device__ short g_cl[BATCH][TOPK];
__device__ u64   g_vab[BATCH][NWORDS];          // validity bitmask
__device__ u64   g_mask[BATCH][TOPK][NWORDS];   // 8 MB suppression matrix

// ---------------------------------------------------------------------------
// Bitwise replica of XLA:GPU's tanh (llvm_ir::EmitFastTanh).
// ---------------------------------------------------------------------------
__device__ __forceinline__ float xla_tanhf(float x) {
    float ax = fabsf(x);
    float xc = fminf(fmaxf(x, -7.90531110763549805f), 7.90531110763549805f);
    float x2 = __fmul_rn(xc, xc);
    float p = -2.76076847742355e-16f;
    p = __fmaf_rn(x2, p, 2.00018790482477e-13f);
    p = __fmaf_rn(x2, p, -8.60467152213735e-11f);
    p = __fmaf_rn(x2, p, 5.12229709037114e-08f);
    p = __fmaf_rn(x2, p, 1.48572235717979e-05f);
    p = __fmaf_rn(x2, p, 6.37261928875436e-04f);
    p = __fmaf_rn(x2, p, 4.89352455891786e-03f);
    p = __fmul_rn(xc, p);
    float q = 1.19825839466702e-06f;
    q = __fmaf_rn(x2, q, 1.18534705686654e-04f);
    q = __fmaf_rn(x2, q, 2.26843463243900e-03f);
    q = __fmaf_rn(x2, q, 4.89352518554385e-03f);
    float r = __fdiv_rn(p, q);
    return (ax < 0.0004f) ? x : r;
}

__device__ __forceinline__ float sigmoid_xla(float x) {
    float t = xla_tanhf(__fmul_rn(0.5f, x));
    return __fmaf_rn(0.5f, t, 0.5f);
}

// ---------------------------------------------------------------------------
// Kernel 1: decode (identical math — measured ~20us).
// ---------------------------------------------------------------------------
__global__ void decode_kernel(const float* __restrict__ in,
                              const float* __restrict__ anchors,
                              float* __restrict__ out) {
    __shared__ float s_out[256 * NATTR];

    int t = blockIdx.x * 256 + threadIdx.x;     // grid sized exactly: no tail
    int b = t / NBOX, n = t % NBOX;
    int a = n / HW,   r = n % HW;
    int gy = r / IW,  gx = r % IW;

    const float* base = in + ((size_t)(b * NA + a) * NATTR) * HW + r;
    float t0 = base[0 * HW];
    float t1 = base[1 * HW];
    float t2 = base[2 * HW];
    float t3 = base[3 * HW];
    float t4 = base[4 * HW];

    float aw = __fdiv_rn(anchors[a * 2 + 0], STRIDE_F);
    float ah = __fdiv_rn(anchors[a * 2 + 1], STRIDE_F);

    float sx = sigmoid_xla(t0);
    float sy = sigmoid_xla(t1);
    float bx = __fmul_rn(__fadd_rn(sx, (float)gx), STRIDE_F);
    float by = __fmul_rn(__fadd_rn(sy, (float)gy), STRIDE_F);
    float bw = __fmul_rn(__fmul_rn(__nv_expf(t2), aw), STRIDE_F);
    float bh = __fmul_rn(__fmul_rn(__nv_expf(t3), ah), STRIDE_F);
    float conf = sigmoid_xla(t4);

    float* so = s_out + threadIdx.x * NATTR;
    so[0] = bx; so[1] = by; so[2] = bw; so[3] = bh; so[4] = conf;

    float bestv = -3.402823466e+38f;
    int best = 0;
#pragma unroll
    for (int c = 0; c < NC; c++) {
        float v = sigmoid_xla(base[(5 + c) * HW]);
        so[5 + c] = v;
        if (v > bestv) { bestv = v; best = c; }
    }
    g_conf[b][n] = conf;
    g_cls[b][n]  = best;
    __syncthreads();

    float* oblk = out + (size_t)blockIdx.x * 256 * NATTR;
    for (int k = threadIdx.x; k < 256 * NATTR; k += 256)
        oblk[k] = s_out[k];
}

// ---------------------------------------------------------------------------
// Top-K: truncated tournament merge. key = (conf_bits<<32)|(~idx);
// desc = conf desc then idx asc. Run r sorted DESC iff popcount(r) even.
// ---------------------------------------------------------------------------
__device__ __forceinline__ u64 cex(u64 a, u64 v, bool lower, bool desc) {
    u64 mx = a > v ? a : v;
    u64 mn = a > v ? v : a;
    return desc ? (lower ? mx : mn) : (lower ? mn : mx);
}

// 2a: fused sort of 4 x 2048-element runs per batch (replaces local_sort +
// merge_pass<1024>). Thread t owns elems t and t+1024 of its run; per-element
// direction bits; j=1024 in-thread, 32<=j<=512 smem, j<=16 shfl.
__global__ void sort2048(void) {
    __shared__ u64 s[2048];
    int c = blockIdx.x, b = blockIdx.y, t = threadIdx.x;
    int base = c * 2048;
    bool dirDesc = ((__popc(c) & 1) == 0);

    u64 r0, r1;
    {
        int i0 = base + t;
        int i1 = base + t + 1024;
        u64 k0 = 0ull, k1 = 0ull;
        if (i0 < NBOX) {
            unsigned cb = __float_as_uint(g_conf[b][i0]);
            k0 = ((u64)cb << 32) | (unsigned)(0xFFFFFFFFu - (unsigned)i0);
        }
        if (i1 < NBOX) {
            unsigned cb = __float_as_uint(g_conf[b][i1]);
            k1 = ((u64)cb << 32) | (unsigned)(0xFFFFFFFFu - (unsigned)i1);
        }
        r0 = k0; r1 = k1;
    }

    for (int k2 = 2; k2 <= 2048; k2 <<= 1) {
        for (int j = k2 >> 1; j > 0; j >>= 1) {
            bool d0 = (((t & k2) == 0) == dirDesc);
            bool d1 = ((((t + 1024) & k2) == 0) == dirDesc);
            if (j == 1024) {
                // partner of elem t is elem t+1024 (same thread); t is lower
                bool sw = d0 ? (r0 < r1) : (r0 > r1);
                if (sw) { u64 tmp = r0; r0 = r1; r1 = tmp; }
            } else if (j >= 32) {
                s[t] = r0; s[t + 1024] = r1;
                __syncthreads();
                u64 v0 = s[t ^ j];
                u64 v1 = s[(t ^ j) + 1024];
                bool lower = (t & j) == 0;
                r0 = cex(r0, v0, lower, d0);
                r1 = cex(r1, v1, lower, d1);
                __syncthreads();
            } else {
                u64 v0 = __shfl_xor_sync(0xFFFFFFFFu, r0, j);
                u64 v1 = __shfl_xor_sync(0xFFFFFFFFu, r1, j);
                bool lower = (t & j) == 0;
                r0 = cex(r0, v0, lower, d0);
                r1 = cex(r1, v1, lower, d1);
            }
        }
    }
    g_runB[b][base + t]        = r0;
    g_runB[b][base + 1024 + t] = r1;
}

// Descending/ascending bitonic merge of a 2048-element bitonic sequence held
// as (r0 = elem t, r1 = elem t+1024). j=1024 in-register; 512..32 smem; 16..1 shfl.
__device__ __forceinline__ void bitonic_merge_2048(u64& r0, u64& r1,
                                                   u64* s, int t, bool dirDesc) {
    {   // j = 1024: in-thread pair, r0 is lower
        bool sw = dirDesc ? (r0 < r1) : (r0 > r1);
        if (sw) { u64 tmp = r0; r0 = r1; r1 = tmp; }
    }
#pragma unroll
    for (int j = 512; j >= 32; j >>= 1) {
        s[t] = r0; s[t + 1024] = r1;
        __syncthreads();
        u64 v0 = s[t ^ j];
        u64 v1 = s[(t ^ j) + 1024];
        bool lower = (t & j) == 0;
        r0 = cex(r0, v0, lower, dirDesc);
        r1 = cex(r1, v1, lower, dirDesc);
        __syncthreads();
    }
#pragma unroll
    for (int j = 16; j >= 1; j >>= 1) {
        u64 v0 = __shfl_xor_sync(0xFFFFFFFFu, r0, j);
        u64 v1 = __shfl_xor_sync(0xFFFFFFFFu, r1, j);
        bool lower = (t & j) == 0;
        r0 = cex(r0, v0, lower, dirDesc);
        r1 = cex(r1, v1, lower, dirDesc);
    }
}

// 2b: truncating merge 2x2048 -> top 2048 (bitonic split), runB -> runA.
__global__ void merge_trunc(void) {
    __shared__ u64 s[2048];
    int m = blockIdx.x, b = blockIdx.y, t = threadIdx.x;
    const u64* A  = g_runB[b] + 2 * m * 2048;
    const u64* Bp = A + 2048;
    u64* outp     = g_runA[b];
    bool dirDesc = ((__popc(m) & 1) == 0);

    u64 a0 = A[t],        b0 = Bp[t];
    u64 a1 = A[t + 1024], b1 = Bp[t + 1024];
    u64 r0 = a0 > b0 ? a0 : b0;    // bitonic split: top half
    u64 r1 = a1 > b1 ? a1 : b1;
    bitonic_merge_2048(r0, r1, s, t, dirDesc);
    outp[m * 2048 + t]        = r0;
    outp[m * 2048 + 1024 + t] = r1;
}

// 2c: final truncating merge (desc) + fused NMS prep. grid (BATCH), 1024 thr.
__global__ void merge_final(const float* __restrict__ out,
                            float* __restrict__ out_topidx) {
    __shared__ u64 s[2048];
    __shared__ unsigned s_vab32[64];
    int b = blockIdx.x, t = threadIdx.x;
    if (t < 64) s_vab32[t] = 0u;

    const u64* A  = g_runA[b];
    const u64* Bp = A + 2048;
    u64 a0 = A[t],        b0 = Bp[t];
    u64 a1 = A[t + 1024], b1 = Bp[t + 1024];
    u64 r0 = a0 > b0 ? a0 : b0;
    u64 r1 = a1 > b1 ? a1 : b1;
    bitonic_merge_2048(r0, r1, s, t, true);

#pragma unroll
    for (int q = 0; q < 2; q++) {
        int i = t + q * 1024;
        u64 kk = q ? r1 : r0;
        int n = (int)(0xFFFFFFFFu - (unsigned)(kk & 0xFFFFFFFFull));
        out_topidx[b * TOPK + i] = (float)n;

        const float* o = out + ((size_t)b * NBOX + n) * NATTR;
        float cx = o[0], cy = o[1], w = o[2], h = o[3];
        float conf = __uint_as_float((unsigned)(kk >> 32));
        float hw2 = __fmul_rn(w, 0.5f);
        float hh2 = __fmul_rn(h, 0.5f);
        float x1 = __fsub_rn(cx, hw2);
        float y1 = __fsub_rn(cy, hh2);
        float x2 = __fadd_rn(cx, hw2);
        float y2 = __fadd_rn(cy, hh2);
        g_x1[b][i] = x1; g_y1[b][i] = y1; g_x2[b][i] = x2; g_y2[b][i] = y2;
        g_ar[b][i] = __fmul_rn(__fadd_rn(__fsub_rn(x2, x1), 1.0f),
                               __fadd_rn(__fsub_rn(y2, y1), 1.0f));
        g_cl[b][i] = (short)g_cls[b][n];
        if (conf >= 0.5f)
            atomicOr(&s_vab32[i >> 5], 1u << (i & 31));
    }
    __syncthreads();
    if (t < 64) ((unsigned*)g_vab[b])[t] = s_vab32[t];
}

// ---------------------------------------------------------------------------
// Kernel 3: suppression mask (R5/R7 version — measured 19.8us).
// ---------------------------------------------------------------------------
__global__ void nms_mask(void) {
    int jb = blockIdx.x, ib = blockIdx.y, b = blockIdx.z;
    if (jb < ib) return;

    __shared__ float jx1[64], jy1[64], jx2[64], jy2[64], jar[64];
    __shared__ u64 s_cm[NC];

    int t = threadIdx.x;
    int j0 = jb * 64;
    if (t < NC) s_cm[t] = 0ull;
    __syncthreads();
    jx1[t] = g_x1[b][j0 + t];
    jy1[t] = g_y1[b][j0 + t];
    jx2[t] = g_x2[b][j0 + t];
    jy2[t] = g_y2[b][j0 + t];
    jar[t] = g_ar[b][j0 + t];
    atomicOr(&s_cm[g_cl[b][j0 + t]], 1ull << t);
    __syncthreads();

    int i = ib * 64 + t;
    float xi1 = g_x1[b][i], yi1 = g_y1[b][i];
    float xi2 = g_x2[b][i], yi2 = g_y2[b][i];
    float ai  = g_ar[b][i];
    short ci  = g_cl[b][i];

    u64 mm = s_cm[ci];
    if (jb == ib) mm = (t < 63) ? (mm & (~0ull << (t + 1))) : 0ull;

    u64 bits = 0ull;
    while (mm) {
        int jj = __ffsll((long long)mm) - 1;
        mm &= mm - 1;
        float ix1 = fmaxf(xi1, jx1[jj]);
        float iy1 = fmaxf(yi1, jy1[jj]);
        float ix2 = fminf(xi2, jx2[jj]);
        float iy2 = fminf(yi2, jy2[jj]);
        float iw = __fadd_rn(__fsub_rn(ix2, ix1), 1.0f); iw = fmaxf(iw, 0.0f);
        float ih = __fadd_rn(__fsub_rn(iy2, iy1), 1.0f); ih = fmaxf(ih, 0.0f);
        float inter = __fmul_rn(iw, ih);
        float den = __fadd_rn(__fsub_rn(__fadd_rn(ai, jar[jj]), inter), 1e-16f);
        float iou = __fdiv_rn(inter, den);
        if (iou >= 0.4f) bits |= 1ull << jj;
    }
    g_mask[b][i][jb] = bits;
}

// ---------------------------------------------------------------------------
// Kernel 4: block-greedy reduce — R7 staged double-buffer version (the one in
// the 186.9us run), verbatim. 256 threads/batch.
// ---------------------------------------------------------------------------
__device__ __forceinline__ void cp16(void* saddr, const void* gaddr) {
    unsigned s = (unsigned)__cvta_generic_to_shared(saddr);
    asm volatile("cp.async.cg.shared.global [%0], [%1], 16;" :: "r"(s), "l"(gaddr));
}

__global__ void nms_reduce(float* __restrict__ keep_out) {
    __shared__ __align__(16) u64 sbuf[2][64][NWORDS];   // 32 KB
    __shared__ unsigned s_rem32[64];
    __shared__ u64 s_vab[NWORDS];
    __shared__ u64 s_keep;

    int b = blockIdx.x, t = threadIdx.x;                // 256 threads
    if (t < 64) s_rem32[t] = 0u;
    if (t < NWORDS) s_vab[t] = g_vab[b][t];

    // stage(blk, buf): 64 rows x 256B = 16 KB = 1024 x 16B chunks, 4/thread
#define STAGE(blk, buf_)                                                    \
    {                                                                       \
        _Pragma("unroll")                                                   \
        for (int k = 0; k < 4; k++) {                                       \
            int chunk = t + 256 * k;                                        \
            int row = chunk >> 4, off = (chunk & 15) * 2;                   \
            cp16(&sbuf[buf_][row][off], &g_mask[b][(blk) * 64 + row][off]); \
        }                                                                   \
    }

    STAGE(0, 0);
    asm volatile("cp.async.commit_group;");
    STAGE(1, 1);
    asm volatile("cp.async.commit_group;");
    asm volatile("cp.async.wait_group 1;");
    __syncthreads();

    for (int bk = 0; bk < NBLK; bk++) {
        int buf = bk & 1;

        // single thread resolves the 64-candidate word greedily
        if (t == 0) {
            u64 rem = (u64)s_rem32[2 * bk] | ((u64)s_rem32[2 * bk + 1] << 32);
            u64 cand = s_vab[bk] & ~rem;
            u64 keep64 = 0ull;
            while (cand) {
                int u = __ffsll((long long)cand) - 1;
                keep64 |= 1ull << u;
                cand &= ~(1ull << u);
                cand &= ~sbuf[buf][u][bk];    // diagonal: bits only for j > u
            }
            s_keep = keep64;
        }
        __syncthreads();
        u64 keep64 = s_keep;

        if (t < 64)
            keep_out[b * TOPK + bk * 64 + t] =
                ((keep64 >> t) & 1ull) ? 1.0f : 0.0f;

        // parallel apply: thread (w, g) ORs kept rows u (u%8==g) into word w
        {
            int w = t & 31, g = t >> 5;
            if (w > bk) {
                u64 kk = keep64 & (0x0101010101010101ull << g);
                u64 part = 0ull;
                while (kk) {
                    int u = __ffsll((long long)kk) - 1;
                    kk &= kk - 1;
                    part |= sbuf[buf][u][w];
                }
                if (part) {
                    unsigned lo = (unsigned)part, hi = (unsigned)(part >> 32);
                    if (lo) atomicOr(&s_rem32[2 * w],     lo);
                    if (hi) atomicOr(&s_rem32[2 * w + 1], hi);
                }
            }
        }
        __syncthreads();          // all sbuf[buf] reads done before restage

        if (bk + 2 < NBLK) STAGE(bk + 2, buf);
        asm volatile("cp.async.commit_group;");
        asm volatile("cp.async.wait_group 1;");
        __syncthreads();
    }
#undef STAGE
}

// ---------------------------------------------------------------------------
// Launch: out = [output(B*NBOX*NATTR) | top_idx(B*TOPK) | keep(B*TOPK)] float32
// ---------------------------------------------------------------------------
extern "C" void kernel_launch(void* const* d_in, const int* in_sizes, int n_in,
                              void* d_out, int out_size) {
    (void)in_sizes; (void)n_in; (void)out_size;
    const float* in      = (const float*)d_in[0];
    const float* anchors = (const float*)d_in[1];
    float* out      = (float*)d_out;
    float* top_out  = out + (size_t)BATCH * NBOX * NATTR;
    float* keep_out = top_out + (size_t)BATCH * TOPK;

    int total = BATCH * NBOX;                 // 129792 = 256 * 507, no tail
    decode_kernel<<<total / 256, 256>>>(in, anchors, out);

    sort2048<<<dim3(4, BATCH), 1024>>>();              // -> runB (d,a,a,d)
    merge_trunc<<<dim3(2, BATCH), 1024>>>();           // runB -> runA (d|a)
    merge_final<<<BATCH, 1024>>>(out, top_out);        // runA -> outputs + prep

    nms_mask<<<dim3(TOPK / 64, TOPK / 64, BATCH), 64>>>();
    nms_reduce<<<BATCH, 256>>>(keep_out);
}

// round 12
// speedup vs baseline: 1.3264x; 1.0785x over previous
#include <cuda_runtime.h>
#include <cstdint>

// Problem constants
#define BATCH 16
#define NA    3
#define NC    20
#define NATTR 25          // 5 + NC
#define IH    52
#define IW    52
#define HW    2704        // IH*IW
#define NBOX  8112        // NA*HW
#define NPAD  8192
#define TOPK  2048
#define NWORDS (TOPK / 64)    // 32 u64 words per suppression row
#define NBLK   (TOPK / 64)    // 32 blocks of 64 candidates
#define STRIDE_F 8.0f

typedef unsigned long long u64;

// Accurate libdevice expf (XLA's f32 exp lowering), immune to --use_fast_math.
extern "C" __device__ float __nv_expf(float);

// Scratch (allocation-free: __device__ globals)
__device__ float g_conf[BATCH][NBOX];
__device__ int   g_cls [BATCH][NBOX];
__device__ u64   g_runA[BATCH][NPAD];
__device__ u64   g_runB[BATCH][NPAD];

// NMS staging
__device__ float g_x1[BATCH][TOPK];
__device__ float g_y1[BATCH][TOPK];
__device__ float g_x2[BATCH][TOPK];
__device__ float g_y2[BATCH][TOPK];
__device__ float g_ar[BATCH][TOPK];
__device__ short g_cl[BATCH][TOPK];
__device__ u64   g_vab[BATCH][NWORDS];          // validity bitmask
__device__ u64   g_mask[BATCH][TOPK][NWORDS];   // suppression matrix (sparse-written)
__device__ unsigned g_rnz[BATCH][TOPK];         // per-row nonzero-word bitmask

// ---------------------------------------------------------------------------
// Bitwise replica of XLA:GPU's tanh (llvm_ir::EmitFastTanh).
// ---------------------------------------------------------------------------
__device__ __forceinline__ float xla_tanhf(float x) {
    float ax = fabsf(x);
    float xc = fminf(fmaxf(x, -7.90531110763549805f), 7.90531110763549805f);
    float x2 = __fmul_rn(xc, xc);
    float p = -2.76076847742355e-16f;
    p = __fmaf_rn(x2, p, 2.00018790482477e-13f);
    p = __fmaf_rn(x2, p, -8.60467152213735e-11f);
    p = __fmaf_rn(x2, p, 5.12229709037114e-08f);
    p = __fmaf_rn(x2, p, 1.48572235717979e-05f);
    p = __fmaf_rn(x2, p, 6.37261928875436e-04f);
    p = __fmaf_rn(x2, p, 4.89352455891786e-03f);
    p = __fmul_rn(xc, p);
    float q = 1.19825839466702e-06f;
    q = __fmaf_rn(x2, q, 1.18534705686654e-04f);
    q = __fmaf_rn(x2, q, 2.26843463243900e-03f);
    q = __fmaf_rn(x2, q, 4.89352518554385e-03f);
    float r = __fdiv_rn(p, q);
    return (ax < 0.0004f) ? x : r;
}

__device__ __forceinline__ float sigmoid_xla(float x) {
    float t = xla_tanhf(__fmul_rn(0.5f, x));
    return __fmaf_rn(0.5f, t, 0.5f);
}

// ---------------------------------------------------------------------------
// Kernel 1: decode (identical math — measured ~20us).
// ---------------------------------------------------------------------------
__global__ void decode_kernel(const float* __restrict__ in,
                              const float* __restrict__ anchors,
                              float* __restrict__ out) {
    __shared__ float s_out[256 * NATTR];

    int t = blockIdx.x * 256 + threadIdx.x;     // grid sized exactly: no tail
    int b = t / NBOX, n = t % NBOX;
    int a = n / HW,   r = n % HW;
    int gy = r / IW,  gx = r % IW;

    const float* base = in + ((size_t)(b * NA + a) * NATTR) * HW + r;
    float t0 = base[0 * HW];
    float t1 = base[1 * HW];
    float t2 = base[2 * HW];
    float t3 = base[3 * HW];
    float t4 = base[4 * HW];

    float aw = __fdiv_rn(anchors[a * 2 + 0], STRIDE_F);
    float ah = __fdiv_rn(anchors[a * 2 + 1], STRIDE_F);

    float sx = sigmoid_xla(t0);
    float sy = sigmoid_xla(t1);
    float bx = __fmul_rn(__fadd_rn(sx, (float)gx), STRIDE_F);
    float by = __fmul_rn(__fadd_rn(sy, (float)gy), STRIDE_F);
    float bw = __fmul_rn(__fmul_rn(__nv_expf(t2), aw), STRIDE_F);
    float bh = __fmul_rn(__fmul_rn(__nv_expf(t3), ah), STRIDE_F);
    float conf = sigmoid_xla(t4);

    float* so = s_out + threadIdx.x * NATTR;
    so[0] = bx; so[1] = by; so[2] = bw; so[3] = bh; so[4] = conf;

    float bestv = -3.402823466e+38f;
    int best = 0;
#pragma unroll
    for (int c = 0; c < NC; c++) {
        float v = sigmoid_xla(base[(5 + c) * HW]);
        so[5 + c] = v;
        if (v > bestv) { bestv = v; best = c; }
    }
    g_conf[b][n] = conf;
    g_cls[b][n]  = best;
    __syncthreads();

    float* oblk = out + (size_t)blockIdx.x * 256 * NATTR;
    for (int k = threadIdx.x; k < 256 * NATTR; k += 256)
        oblk[k] = s_out[k];
}

// ---------------------------------------------------------------------------
// Top-K: truncated tournament merge (R7 chain, measured-best).
// key = (conf_bits<<32)|(~idx); desc = conf desc then idx asc.
// Run r sorted DESC iff popcount(r) even.
// ---------------------------------------------------------------------------
__device__ __forceinline__ u64 cex(u64 a, u64 v, bool lower, bool desc) {
    u64 mx = a > v ? a : v;
    u64 mn = a > v ? v : a;
    return desc ? (lower ? mx : mn) : (lower ? mn : mx);
}

// 2a: local sort of 8 x 1024 runs per batch; element register-resident.
__global__ void local_sort(void) {
    __shared__ u64 s[1024];
    int c = blockIdx.x, b = blockIdx.y, t = threadIdx.x;
    int i = c * 1024 + t;
    u64 mine = 0ull;
    if (i < NBOX) {
        unsigned cb = __float_as_uint(g_conf[b][i]);
        mine = ((u64)cb << 32) | (unsigned)(0xFFFFFFFFu - (unsigned)i);
    }
    bool dirDesc = ((__popc(c) & 1) == 0);

    for (int k2 = 2; k2 <= 1024; k2 <<= 1) {
        for (int j = k2 >> 1; j > 0; j >>= 1) {
            bool descb = (((t & k2) == 0) == dirDesc);
            bool lower = (t & j) == 0;
            if (j >= 32) {
                s[t] = mine;
                __syncthreads();
                u64 v = s[t ^ j];
                mine = cex(mine, v, lower, descb);
                __syncthreads();
            } else {
                u64 v = __shfl_xor_sync(0xFFFFFFFFu, mine, j);
                mine = cex(mine, v, lower, descb);
            }
        }
    }
    g_runA[b][c * 1024 + t] = mine;
}

// Bitonic merge of a 2048-elem bitonic sequence (r0 = elem t, r1 = t+1024).
__device__ __forceinline__ void bitonic_merge_2048(u64& r0, u64& r1,
                                                   u64* s, int t, bool dirDesc) {
    {   // j = 1024: in-thread pair, r0 is lower
        bool sw = dirDesc ? (r0 < r1) : (r0 > r1);
        if (sw) { u64 tmp = r0; r0 = r1; r1 = tmp; }
    }
#pragma unroll
    for (int j = 512; j >= 32; j >>= 1) {
        s[t] = r0; s[t + 1024] = r1;
        __syncthreads();
        u64 v0 = s[t ^ j];
        u64 v1 = s[(t ^ j) + 1024];
        bool lower = (t & j) == 0;
        r0 = cex(r0, v0, lower, dirDesc);
        r1 = cex(r1, v1, lower, dirDesc);
        __syncthreads();
    }
#pragma unroll
    for (int j = 16; j >= 1; j >>= 1) {
        u64 v0 = __shfl_xor_sync(0xFFFFFFFFu, r0, j);
        u64 v1 = __shfl_xor_sync(0xFFFFFFFFu, r1, j);
        bool lower = (t & j) == 0;
        r0 = cex(r0, v0, lower, dirDesc);
        r1 = cex(r1, v1, lower, dirDesc);
    }
}

// 2b: merge pass. RUNLEN=1024: full merge; RUNLEN=2048: truncating merge.
template<int RUNLEN, int SRCA>
__global__ void merge_pass(void) {
    __shared__ u64 s[2048];
    int m = blockIdx.x, b = blockIdx.y, t = threadIdx.x;
    const u64* in = SRCA ? g_runA[b] : g_runB[b];
    u64* outp     = SRCA ? g_runB[b] : g_runA[b];
    const u64* A  = in + 2 * m * RUNLEN;
    const u64* Bp = A + RUNLEN;
    bool dirDesc = ((__popc(m) & 1) == 0);

    u64 r0, r1;
    if (RUNLEN == 1024) {
        r0 = A[t];
        r1 = Bp[t];
    } else {
        u64 a0 = A[t],        b0 = Bp[t];
        u64 a1 = A[t + 1024], b1 = Bp[t + 1024];
        r0 = a0 > b0 ? a0 : b0;    // bitonic split: top half
        r1 = a1 > b1 ? a1 : b1;
    }
    bitonic_merge_2048(r0, r1, s, t, dirDesc);
    outp[m * 2048 + t]        = r0;
    outp[m * 2048 + 1024 + t] = r1;
}

// 2c: final truncating merge (desc) + fused NMS prep + rnz zero.
__global__ void merge_final(const float* __restrict__ out,
                            float* __restrict__ out_topidx) {
    __shared__ u64 s[2048];
    __shared__ unsigned s_vab32[64];
    int b = blockIdx.x, t = threadIdx.x;
    if (t < 64) s_vab32[t] = 0u;

    const u64* A  = g_runA[b];
    const u64* Bp = A + 2048;
    u64 a0 = A[t],        b0 = Bp[t];
    u64 a1 = A[t + 1024], b1 = Bp[t + 1024];
    u64 r0 = a0 > b0 ? a0 : b0;
    u64 r1 = a1 > b1 ? a1 : b1;
    bitonic_merge_2048(r0, r1, s, t, true);

#pragma unroll
    for (int q = 0; q < 2; q++) {
        int i = t + q * 1024;
        u64 kk = q ? r1 : r0;
        int n = (int)(0xFFFFFFFFu - (unsigned)(kk & 0xFFFFFFFFull));
        out_topidx[b * TOPK + i] = (float)n;
        g_rnz[b][i] = 0u;

        const float* o = out + ((size_t)b * NBOX + n) * NATTR;
        float cx = o[0], cy = o[1], w = o[2], h = o[3];
        float conf = __uint_as_float((unsigned)(kk >> 32));
        float hw2 = __fmul_rn(w, 0.5f);
        float hh2 = __fmul_rn(h, 0.5f);
        float x1 = __fsub_rn(cx, hw2);
        float y1 = __fsub_rn(cy, hh2);
        float x2 = __fadd_rn(cx, hw2);
        float y2 = __fadd_rn(cy, hh2);
        g_x1[b][i] = x1; g_y1[b][i] = y1; g_x2[b][i] = x2; g_y2[b][i] = y2;
        g_ar[b][i] = __fmul_rn(__fadd_rn(__fsub_rn(x2, x1), 1.0f),
                               __fadd_rn(__fsub_rn(y2, y1), 1.0f));
        g_cl[b][i] = (short)g_cls[b][n];
        if (conf >= 0.5f)
            atomicOr(&s_vab32[i >> 5], 1u << (i & 31));
    }
    __syncthreads();
    if (t < 64) ((unsigned*)g_vab[b])[t] = s_vab32[t];
}

// ---------------------------------------------------------------------------
// Kernel 3: suppression mask (R5/R7 measured version) + sparse writes + rnz.
// Diagonal word always written; off-diagonal only when nonzero (then rnz bit
// set). Zero off-diag words are never read downstream (rnz-guarded).
// ---------------------------------------------------------------------------
__global__ void nms_mask(void) {
    int jb = blockIdx.x, ib = blockIdx.y, b = blockIdx.z;
    if (jb < ib) return;

    __shared__ float jx1[64], jy1[64], jx2[64], jy2[64], jar[64];
    __shared__ u64 s_cm[NC];

    int t = threadIdx.x;
    int j0 = jb * 64;
    if (t < NC) s_cm[t] = 0ull;
    __syncthreads();
    jx1[t] = g_x1[b][j0 + t];
    jy1[t] = g_y1[b][j0 + t];
    jx2[t] = g_x2[b][j0 + t];
    jy2[t] = g_y2[b][j0 + t];
    jar[t] = g_ar[b][j0 + t];
    atomicOr(&s_cm[g_cl[b][j0 + t]], 1ull << t);
    __syncthreads();

    int i = ib * 64 + t;
    float xi1 = g_x1[b][i], yi1 = g_y1[b][i];
    float xi2 = g_x2[b][i], yi2 = g_y2[b][i];
    float ai  = g_ar[b][i];
    short ci  = g_cl[b][i];

    u64 mm = s_cm[ci];
    if (jb == ib) mm = (t < 63) ? (mm & (~0ull << (t + 1))) : 0ull;

    u64 bits = 0ull;
    while (mm) {
        int jj = __ffsll((long long)mm) - 1;
        mm &= mm - 1;
        float ix1 = fmaxf(xi1, jx1[jj]);
        float iy1 = fmaxf(yi1, jy1[jj]);
        float ix2 = fminf(xi2, jx2[jj]);
        float iy2 = fminf(yi2, jy2[jj]);
        float iw = __fadd_rn(__fsub_rn(ix2, ix1), 1.0f); iw = fmaxf(iw, 0.0f);
        float ih = __fadd_rn(__fsub_rn(iy2, iy1), 1.0f); ih = fmaxf(ih, 0.0f);
        float inter = __fmul_rn(iw, ih);
        float den = __fadd_rn(__fsub_rn(__fadd_rn(ai, jar[jj]), inter), 1e-16f);
        float iou = __fdiv_rn(inter, den);
        if (iou >= 0.4f) bits |= 1ull << jj;
    }
    if (jb == ib) {
        g_mask[b][i][jb] = bits;            // diagonal always valid
    } else if (bits) {
        g_mask[b][i][jb] = bits;
        atomicOr(&g_rnz[b][i], 1u << jb);
    }
}

// ---------------------------------------------------------------------------
// Kernel 4: sparse block-greedy reduce. Diagonals + rnz preloaded; resolve
// iterates only rows with NONZERO diagonal (act ⊆ cand invariant => every
// popped element is kept; final keep = cand, exactly greedy). Apply touches
// only kept rows with nonzero later words, loads guarded by rnz.
// ---------------------------------------------------------------------------
__global__ void nms_reduce(float* __restrict__ keep_out) {
    __shared__ u64 diagAll[NBLK][64];       // 16 KB
    __shared__ unsigned s_rnz[TOPK];        // 8 KB
    __shared__ u64 s_rem[NWORDS];
    __shared__ u64 s_act[NBLK];             // rows with nonzero diag word
    __shared__ u64 s_offnz[NBLK];           // rows with any nonzero word > bk
    __shared__ u64 s_vab[NWORDS];
    __shared__ u64 s_keep;

    int b = blockIdx.x, t = threadIdx.x;    // 256 threads
    if (t < NWORDS) {
        s_rem[t] = 0ull;
        s_act[t] = 0ull;
        s_offnz[t] = 0ull;
        s_vab[t] = g_vab[b][t];
    }
    __syncthreads();

    for (int k = t; k < TOPK; k += 256) {
        int bk = k >> 6, u = k & 63;
        u64 d = g_mask[b][k][bk];
        diagAll[bk][u] = d;
        if (d) atomicOr(&s_act[bk], 1ull << u);
        unsigned rz = g_rnz[b][k];
        s_rnz[k] = rz;
        unsigned gt = (bk < 31) ? (0xFFFFFFFFu << (bk + 1)) : 0u;
        if (rz & gt) atomicOr(&s_offnz[bk], 1ull << u);
    }
    __syncthreads();

    for (int bk = 0; bk < NBLK; bk++) {
        // resolve: iterate only active suppressor candidates
        if (t == 0) {
            u64 cand = s_vab[bk] & ~s_rem[bk];
            u64 act = cand & s_act[bk];
            while (act) {
                int u = __ffsll((long long)act) - 1;
                u64 d = diagAll[bk][u];
                act &= ~(1ull << u);
                cand &= ~d;                 // u is kept; suppress later elems
                act &= ~d;
            }
            s_keep = cand;                  // exact greedy keep set
        }
        __syncthreads();
        u64 k64 = s_keep;

        if (t < 64)
            keep_out[b * TOPK + bk * 64 + t] =
                ((k64 >> t) & 1ull) ? 1.0f : 0.0f;

        // apply: only kept rows with nonzero later words; rnz-guarded loads
        if (t < NWORDS) {
            int w = t;
            u64 ka = k64 & s_offnz[bk];
            if (w > bk && ka) {
                u64 part = 0ull;
                while (ka) {
                    int u = __ffsll((long long)ka) - 1;
                    ka &= ka - 1;
                    int row = bk * 64 + u;
                    if ((s_rnz[row] >> w) & 1u)
                        part |= g_mask[b][row][w];
                }
                if (part) atomicOr(&s_rem[w], part);
            }
        }
        __syncthreads();
    }
}

// ---------------------------------------------------------------------------
// Launch: out = [output(B*NBOX*NATTR) | top_idx(B*TOPK) | keep(B*TOPK)] float32
// ---------------------------------------------------------------------------
extern "C" void kernel_launch(void* const* d_in, const int* in_sizes, int n_in,
                              void* d_out, int out_size) {
    (void)in_sizes; (void)n_in; (void)out_size;
    const float* in      = (const float*)d_in[0];
    const float* anchors = (const float*)d_in[1];
    float* out      = (float*)d_out;
    float* top_out  = out + (size_t)BATCH * NBOX * NATTR;
    float* keep_out = top_out + (size_t)BATCH * TOPK;

    int total = BATCH * NBOX;                 // 129792 = 256 * 507, no tail
    decode_kernel<<<total / 256, 256>>>(in, anchors, out);

    local_sort<<<dim3(8, BATCH), 1024>>>();
    merge_pass<1024, 1><<<dim3(4, BATCH), 1024>>>();   // A -> B (full merges)
    merge_pass<2048, 0><<<dim3(2, BATCH), 1024>>>();   // B -> A (truncating)
    merge_final<<<BATCH, 1024>>>(out, top_out);        // A -> outputs + prep

    nms_mask<<<dim3(TOPK / 64, TOPK / 64, BATCH), 64>>>();
    nms_reduce<<<BATCH, 256>>>(keep_out);
}

// round 13
// speedup vs baseline: 1.3347x; 1.0062x over previous
#include <cuda_runtime.h>
#include <cstdint>

// Problem constants
#define BATCH 16
#define NA    3
#define NC    20
#define NATTR 25          // 5 + NC
#define IH    52
#define IW    52
#define HW    2704        // IH*IW
#define NBOX  8112        // NA*HW
#define NPAD  8192
#define TOPK  2048
#define NWORDS (TOPK / 64)    // 32 u64 words per suppression row
#define NBLK   (TOPK / 64)    // 32 blocks of 64 candidates
#define STRIDE_F 8.0f

typedef unsigned long long u64;

// Accurate libdevice expf (XLA's f32 exp lowering), immune to --use_fast_math.
extern "C" __device__ float __nv_expf(float);

// Scratch (allocation-free: __device__ globals)
__device__ float g_conf[BATCH][NBOX];
__device__ int   g_cls [BATCH][NBOX];
__device__ u64   g_runA[BATCH][NPAD];
__device__ u64   g_runB[BATCH][NPAD];
__device__ int   g_scnt[BATCH][8];              // tournament counters

// NMS staging
__device__ float g_x1[BATCH][TOPK];
__device__ float g_y1[BATCH][TOPK];
__device__ float g_x2[BATCH][TOPK];
__device__ float g_y2[BATCH][TOPK];
__device__ float g_ar[BATCH][TOPK];
__device__ short g_cl[BATCH][TOPK];
__device__ u64   g_vab[BATCH][NWORDS];          // validity bitmask
__device__ u64   g_mask[BATCH][TOPK][NWORDS];   // suppression matrix (sparse-written)
__device__ unsigned g_rnz[BATCH][TOPK];         // per-row nonzero-word bitmask

// ---------------------------------------------------------------------------
// Bitwise replica of XLA:GPU's tanh (llvm_ir::EmitFastTanh).
// ---------------------------------------------------------------------------
__device__ __forceinline__ float xla_tanhf(float x) {
    float ax = fabsf(x);
    float xc = fminf(fmaxf(x, -7.90531110763549805f), 7.90531110763549805f);
    float x2 = __fmul_rn(xc, xc);
    float p = -2.76076847742355e-16f;
    p = __fmaf_rn(x2, p, 2.00018790482477e-13f);
    p = __fmaf_rn(x2, p, -8.60467152213735e-11f);
    p = __fmaf_rn(x2, p, 5.12229709037114e-08f);
    p = __fmaf_rn(x2, p, 1.48572235717979e-05f);
    p = __fmaf_rn(x2, p, 6.37261928875436e-04f);
    p = __fmaf_rn(x2, p, 4.89352455891786e-03f);
    p = __fmul_rn(xc, p);
    float q = 1.19825839466702e-06f;
    q = __fmaf_rn(x2, q, 1.18534705686654e-04f);
    q = __fmaf_rn(x2, q, 2.26843463243900e-03f);
    q = __fmaf_rn(x2, q, 4.89352518554385e-03f);
    float r = __fdiv_rn(p, q);
    return (ax < 0.0004f) ? x : r;
}

__device__ __forceinline__ float sigmoid_xla(float x) {
    float t = xla_tanhf(__fmul_rn(0.5f, x));
    return __fmaf_rn(0.5f, t, 0.5f);
}

// ---------------------------------------------------------------------------
// Kernel 1: decode (identical math — measured ~20us). CTA 0 also zeroes the
// tournament counters for this replay (stream-ordered before sort launch).
// ---------------------------------------------------------------------------
__global__ void decode_kernel(const float* __restrict__ in,
                              const float* __restrict__ anchors,
                              float* __restrict__ out) {
    __shared__ float s_out[256 * NATTR];

    if (blockIdx.x == 0 && threadIdx.x < BATCH * 8)
        ((int*)g_scnt)[threadIdx.x] = 0;

    int t = blockIdx.x * 256 + threadIdx.x;     // grid sized exactly: no tail
    int b = t / NBOX, n = t % NBOX;
    int a = n / HW,   r = n % HW;
    int gy = r / IW,  gx = r % IW;

    const float* base = in + ((size_t)(b * NA + a) * NATTR) * HW + r;
    float t0 = base[0 * HW];
    float t1 = base[1 * HW];
    float t2 = base[2 * HW];
    float t3 = base[3 * HW];
    float t4 = base[4 * HW];

    float aw = __fdiv_rn(anchors[a * 2 + 0], STRIDE_F);
    float ah = __fdiv_rn(anchors[a * 2 + 1], STRIDE_F);

    float sx = sigmoid_xla(t0);
    float sy = sigmoid_xla(t1);
    float bx = __fmul_rn(__fadd_rn(sx, (float)gx), STRIDE_F);
    float by = __fmul_rn(__fadd_rn(sy, (float)gy), STRIDE_F);
    float bw = __fmul_rn(__fmul_rn(__nv_expf(t2), aw), STRIDE_F);
    float bh = __fmul_rn(__fmul_rn(__nv_expf(t3), ah), STRIDE_F);
    float conf = sigmoid_xla(t4);

    float* so = s_out + threadIdx.x * NATTR;
    so[0] = bx; so[1] = by; so[2] = bw; so[3] = bh; so[4] = conf;

    float bestv = -3.402823466e+38f;
    int best = 0;
#pragma unroll
    for (int c = 0; c < NC; c++) {
        float v = sigmoid_xla(base[(5 + c) * HW]);
        so[5 + c] = v;
        if (v > bestv) { bestv = v; best = c; }
    }
    g_conf[b][n] = conf;
    g_cls[b][n]  = best;
    __syncthreads();

    float* oblk = out + (size_t)blockIdx.x * 256 * NATTR;
    for (int k = threadIdx.x; k < 256 * NATTR; k += 256)
        oblk[k] = s_out[k];
}

// ---------------------------------------------------------------------------
// Top-K machinery (verbatim R7/R12 pieces).
// key = (conf_bits<<32)|(~idx); desc = conf desc then idx asc.
// Run r at any level sorted DESC iff popcount(r) even.
// ---------------------------------------------------------------------------
__device__ __forceinline__ u64 cex(u64 a, u64 v, bool lower, bool desc) {
    u64 mx = a > v ? a : v;
    u64 mn = a > v ? v : a;
    return desc ? (lower ? mx : mn) : (lower ? mn : mx);
}

__device__ __forceinline__ void bitonic_merge_2048(u64& r0, u64& r1,
                                                   u64* s, int t, bool dirDesc) {
    {   // j = 1024: in-thread pair, r0 is lower
        bool sw = dirDesc ? (r0 < r1) : (r0 > r1);
        if (sw) { u64 tmp = r0; r0 = r1; r1 = tmp; }
    }
#pragma unroll
    for (int j = 512; j >= 32; j >>= 1) {
        s[t] = r0; s[t + 1024] = r1;
        __syncthreads();
        u64 v0 = s[t ^ j];
        u64 v1 = s[(t ^ j) + 1024];
        bool lower = (t & j) == 0;
        r0 = cex(r0, v0, lower, dirDesc);
        r1 = cex(r1, v1, lower, dirDesc);
        __syncthreads();
    }
#pragma unroll
    for (int j = 16; j >= 1; j >>= 1) {
        u64 v0 = __shfl_xor_sync(0xFFFFFFFFu, r0, j);
        u64 v1 = __shfl_xor_sync(0xFFFFFFFFu, r1, j);
        bool lower = (t & j) == 0;
        r0 = cex(r0, v0, lower, dirDesc);
        r1 = cex(r1, v1, lower, dirDesc);
    }
}

// Fused tournament sort: grid (8, BATCH), 1024 threads. Each CTA sorts its
// 1024-run (verbatim local_sort), then the LAST CTA of each pair/quad/final
// stage continues with the verbatim merge code. threadFenceReduction pattern:
// writes -> __threadfence -> atomicAdd; second arriver owns the merge. No
// spinning anywhere, so no co-residency requirement.
__global__ void sort_fused(const float* __restrict__ out,
                           float* __restrict__ out_topidx) {
    __shared__ u64 s[2048];
    __shared__ int s_go;
    __shared__ unsigned s_vab32[64];
    int c = blockIdx.x, b = blockIdx.y, t = threadIdx.x;

    // ---- phase 1: local sort of run c (verbatim local_sort) ----
    {
        int i = c * 1024 + t;
        u64 mine = 0ull;
        if (i < NBOX) {
            unsigned cb = __float_as_uint(g_conf[b][i]);
            mine = ((u64)cb << 32) | (unsigned)(0xFFFFFFFFu - (unsigned)i);
        }
        bool dirDesc = ((__popc(c) & 1) == 0);

        for (int k2 = 2; k2 <= 1024; k2 <<= 1) {
            for (int j = k2 >> 1; j > 0; j >>= 1) {
                bool descb = (((t & k2) == 0) == dirDesc);
                bool lower = (t & j) == 0;
                if (j >= 32) {
                    s[t] = mine;
                    __syncthreads();
                    u64 v = s[t ^ j];
                    mine = cex(mine, v, lower, descb);
                    __syncthreads();
                } else {
                    u64 v = __shfl_xor_sync(0xFFFFFFFFu, mine, j);
                    mine = cex(mine, v, lower, descb);
                }
            }
        }
        g_runA[b][c * 1024 + t] = mine;
    }
    __threadfence();
    __syncthreads();

    // ---- continuation 1: pair merge (verbatim merge_pass<1024,1>) ----
    int pc = c >> 1;
    if (t == 0) s_go = atomicAdd(&g_scnt[b][pc], 1);
    __syncthreads();
    if (s_go == 0) return;          // first arriver retires
    __threadfence();
    {
        const u64* A  = g_runA[b] + 2 * pc * 1024;
        const u64* Bp = A + 1024;
        bool dirDesc = ((__popc(pc) & 1) == 0);
        u64 r0 = A[t];
        u64 r1 = Bp[t];
        bitonic_merge_2048(r0, r1, s, t, dirDesc);
        g_runB[b][pc * 2048 + t]        = r0;
        g_runB[b][pc * 2048 + 1024 + t] = r1;
    }
    __threadfence();
    __syncthreads();

    // ---- continuation 2: quad truncating merge (verbatim merge_pass<2048,0>) ----
    int qc = pc >> 1;
    if (t == 0) s_go = atomicAdd(&g_scnt[b][4 + qc], 1);
    __syncthreads();
    if (s_go == 0) return;
    __threadfence();
    {
        const u64* A  = g_runB[b] + 2 * qc * 2048;
        const u64* Bp = A + 2048;
        bool dirDesc = ((__popc(qc) & 1) == 0);
        u64 a0 = A[t],        b0 = Bp[t];
        u64 a1 = A[t + 1024], b1 = Bp[t + 1024];
        u64 r0 = a0 > b0 ? a0 : b0;    // bitonic split: top half
        u64 r1 = a1 > b1 ? a1 : b1;
        bitonic_merge_2048(r0, r1, s, t, dirDesc);
        g_runA[b][qc * 2048 + t]        = r0;
        g_runA[b][qc * 2048 + 1024 + t] = r1;
    }
    __threadfence();
    __syncthreads();

    // ---- continuation 3: final truncating merge + prep (verbatim merge_final) ----
    if (t == 0) s_go = atomicAdd(&g_scnt[b][6], 1);
    __syncthreads();
    if (s_go == 0) return;
    __threadfence();

    if (t < 64) s_vab32[t] = 0u;
    u64 fr0, fr1;
    {
        const u64* A  = g_runA[b];
        const u64* Bp = A + 2048;
        u64 a0 = A[t],        b0 = Bp[t];
        u64 a1 = A[t + 1024], b1 = Bp[t + 1024];
        fr0 = a0 > b0 ? a0 : b0;
        fr1 = a1 > b1 ? a1 : b1;
        bitonic_merge_2048(fr0, fr1, s, t, true);
    }

#pragma unroll
    for (int q = 0; q < 2; q++) {
        int i = t + q * 1024;
        u64 kk = q ? fr1 : fr0;
        int n = (int)(0xFFFFFFFFu - (unsigned)(kk & 0xFFFFFFFFull));
        out_topidx[b * TOPK + i] = (float)n;
        g_rnz[b][i] = 0u;

        const float* o = out + ((size_t)b * NBOX + n) * NATTR;
        float cx = o[0], cy = o[1], w = o[2], h = o[3];
        float conf = __uint_as_float((unsigned)(kk >> 32));
        float hw2 = __fmul_rn(w, 0.5f);
        float hh2 = __fmul_rn(h, 0.5f);
        float x1 = __fsub_rn(cx, hw2);
        float y1 = __fsub_rn(cy, hh2);
        float x2 = __fadd_rn(cx, hw2);
        float y2 = __fadd_rn(cy, hh2);
        g_x1[b][i] = x1; g_y1[b][i] = y1; g_x2[b][i] = x2; g_y2[b][i] = y2;
        g_ar[b][i] = __fmul_rn(__fadd_rn(__fsub_rn(x2, x1), 1.0f),
                               __fadd_rn(__fsub_rn(y2, y1), 1.0f));
        g_cl[b][i] = (short)g_cls[b][n];
        if (conf >= 0.5f)
            atomicOr(&s_vab32[i >> 5], 1u << (i & 31));
    }
    __syncthreads();
    if (t < 64) ((unsigned*)g_vab[b])[t] = s_vab32[t];
}

// ---------------------------------------------------------------------------
// Kernel 3: suppression mask (verbatim R12 sparse version).
// ---------------------------------------------------------------------------
__global__ void nms_mask(void) {
    int jb = blockIdx.x, ib = blockIdx.y, b = blockIdx.z;
    if (jb < ib) return;

    __shared__ float jx1[64], jy1[64], jx2[64], jy2[64], jar[64];
    __shared__ u64 s_cm[NC];

    int t = threadIdx.x;
    int j0 = jb * 64;
    if (t < NC) s_cm[t] = 0ull;
    __syncthreads();
    jx1[t] = g_x1[b][j0 + t];
    jy1[t] = g_y1[b][j0 + t];
    jx2[t] = g_x2[b][j0 + t];
    jy2[t] = g_y2[b][j0 + t];
    jar[t] = g_ar[b][j0 + t];
    atomicOr(&s_cm[g_cl[b][j0 + t]], 1ull << t);
    __syncthreads();

    int i = ib * 64 + t;
    float xi1 = g_x1[b][i], yi1 = g_y1[b][i];
    float xi2 = g_x2[b][i], yi2 = g_y2[b][i];
    float ai  = g_ar[b][i];
    short ci  = g_cl[b][i];

    u64 mm = s_cm[ci];
    if (jb == ib) mm = (t < 63) ? (mm & (~0ull << (t + 1))) : 0ull;

    u64 bits = 0ull;
    while (mm) {
        int jj = __ffsll((long long)mm) - 1;
        mm &= mm - 1;
        float ix1 = fmaxf(xi1, jx1[jj]);
        float iy1 = fmaxf(yi1, jy1[jj]);
        float ix2 = fminf(xi2, jx2[jj]);
        float iy2 = fminf(yi2, jy2[jj]);
        float iw = __fadd_rn(__fsub_rn(ix2, ix1), 1.0f); iw = fmaxf(iw, 0.0f);
        float ih = __fadd_rn(__fsub_rn(iy2, iy1), 1.0f); ih = fmaxf(ih, 0.0f);
        float inter = __fmul_rn(iw, ih);
        float den = __fadd_rn(__fsub_rn(__fadd_rn(ai, jar[jj]), inter), 1e-16f);
        float iou = __fdiv_rn(inter, den);
        if (iou >= 0.4f) bits |= 1ull << jj;
    }
    if (jb == ib) {
        g_mask[b][i][jb] = bits;            // diagonal always valid
    } else if (bits) {
        g_mask[b][i][jb] = bits;
        atomicOr(&g_rnz[b][i], 1u << jb);
    }
}

// ---------------------------------------------------------------------------
// Kernel 4: sparse block-greedy reduce (verbatim R12).
// ---------------------------------------------------------------------------
__global__ void nms_reduce(float* __restrict__ keep_out) {
    __shared__ u64 diagAll[NBLK][64];       // 16 KB
    __shared__ unsigned s_rnz[TOPK];        // 8 KB
    __shared__ u64 s_rem[NWORDS];
    __shared__ u64 s_act[NBLK];
    __shared__ u64 s_offnz[NBLK];
    __shared__ u64 s_vab[NWORDS];
    __shared__ u64 s_keep;

    int b = blockIdx.x, t = threadIdx.x;    // 256 threads
    if (t < NWORDS) {
        s_rem[t] = 0ull;
        s_act[t] = 0ull;
        s_offnz[t] = 0ull;
        s_vab[t] = g_vab[b][t];
    }
    __syncthreads();

    for (int k = t; k < TOPK; k += 256) {
        int bk = k >> 6, u = k & 63;
        u64 d = g_mask[b][k][bk];
        diagAll[bk][u] = d;
        if (d) atomicOr(&s_act[bk], 1ull << u);
        unsigned rz = g_rnz[b][k];
        s_rnz[k] = rz;
        unsigned gt = (bk < 31) ? (0xFFFFFFFFu << (bk + 1)) : 0u;
        if (rz & gt) atomicOr(&s_offnz[bk], 1ull << u);
    }
    __syncthreads();

    for (int bk = 0; bk < NBLK; bk++) {
        if (t == 0) {
            u64 cand = s_vab[bk] & ~s_rem[bk];
            u64 act = cand & s_act[bk];
            while (act) {
                int u = __ffsll((long long)act) - 1;
                u64 d = diagAll[bk][u];
                act &= ~(1ull << u);
                cand &= ~d;
                act &= ~d;
            }
            s_keep = cand;
        }
        __syncthreads();
        u64 k64 = s_keep;

        if (t < 64)
            keep_out[b * TOPK + bk * 64 + t] =
                ((k64 >> t) & 1ull) ? 1.0f : 0.0f;

        if (t < NWORDS) {
            int w = t;
            u64 ka = k64 & s_offnz[bk];
            if (w > bk && ka) {
                u64 part = 0ull;
                while (ka) {
                    int u = __ffsll((long long)ka) - 1;
                    ka &= ka - 1;
                    int row = bk * 64 + u;
                    if ((s_rnz[row] >> w) & 1u)
                        part |= g_mask[b][row][w];
                }
                if (part) atomicOr(&s_rem[w], part);
            }
        }
        __syncthreads();
    }
}

// ---------------------------------------------------------------------------
// Launch: out = [output(B*NBOX*NATTR) | top_idx(B*TOPK) | keep(B*TOPK)] float32
// ---------------------------------------------------------------------------
extern "C" void kernel_launch(void* const* d_in, const int* in_sizes, int n_in,
                              void* d_out, int out_size) {
    (void)in_sizes; (void)n_in; (void)out_size;
    const float* in      = (const float*)d_in[0];
    const float* anchors = (const float*)d_in[1];
    float* out      = (float*)d_out;
    float* top_out  = out + (size_t)BATCH * NBOX * NATTR;
    float* keep_out = top_out + (size_t)BATCH * TOPK;

    int total = BATCH * NBOX;                 // 129792 = 256 * 507, no tail
    decode_kernel<<<total / 256, 256>>>(in, anchors, out);

    sort_fused<<<dim3(8, BATCH), 1024>>>(out, top_out);

    nms_mask<<<dim3(TOPK / 64, TOPK / 64, BATCH), 64>>>();
    nms_reduce<<<BATCH, 256>>>(keep_out);
}

// round 14
// speedup vs baseline: 2.4610x; 1.8439x over previous
#include <cuda_runtime.h>
#include <cstdint>

// Problem constants
#define BATCH 16
#define NA    3
#define NC    20
#define NATTR 25          // 5 + NC
#define IH    52
#define IW    52
#define HW    2704        // IH*IW
#define NBOX  8112        // NA*HW
#define NPAD  8192
#define TOPK  2048
#define NWORDS (TOPK / 64)    // 32 u64 words per suppression row
#define NBLK   (TOPK / 64)    // 32 blocks of 64 candidates
#define MAXE  2048            // edge-list capacity (fallback if exceeded)
#define STRIDE_F 8.0f

typedef unsigned long long u64;

// Accurate libdevice expf (XLA's f32 exp lowering), immune to --use_fast_math.
extern "C" __device__ float __nv_expf(float);

// Scratch (allocation-free: __device__ globals)
__device__ float g_conf[BATCH][NBOX];
__device__ int   g_cls [BATCH][NBOX];
__device__ u64   g_runA[BATCH][NPAD];
__device__ u64   g_runB[BATCH][NPAD];
__device__ int   g_scnt[BATCH][8];              // tournament counters

// NMS staging
__device__ float g_x1[BATCH][TOPK];
__device__ float g_y1[BATCH][TOPK];
__device__ float g_x2[BATCH][TOPK];
__device__ float g_y2[BATCH][TOPK];
__device__ float g_ar[BATCH][TOPK];
__device__ short g_cl[BATCH][TOPK];
__device__ u64   g_vab[BATCH][NWORDS];          // validity bitmask
__device__ u64   g_mask[BATCH][TOPK][NWORDS];   // suppression matrix (sparse-written)
__device__ unsigned g_rnz[BATCH][TOPK];         // per-row nonzero-word bitmask

// ---------------------------------------------------------------------------
// Bitwise replica of XLA:GPU's tanh (llvm_ir::EmitFastTanh).
// ---------------------------------------------------------------------------
__device__ __forceinline__ float xla_tanhf(float x) {
    float ax = fabsf(x);
    float xc = fminf(fmaxf(x, -7.90531110763549805f), 7.90531110763549805f);
    float x2 = __fmul_rn(xc, xc);
    float p = -2.76076847742355e-16f;
    p = __fmaf_rn(x2, p, 2.00018790482477e-13f);
    p = __fmaf_rn(x2, p, -8.60467152213735e-11f);
    p = __fmaf_rn(x2, p, 5.12229709037114e-08f);
    p = __fmaf_rn(x2, p, 1.48572235717979e-05f);
    p = __fmaf_rn(x2, p, 6.37261928875436e-04f);
    p = __fmaf_rn(x2, p, 4.89352455891786e-03f);
    p = __fmul_rn(xc, p);
    float q = 1.19825839466702e-06f;
    q = __fmaf_rn(x2, q, 1.18534705686654e-04f);
    q = __fmaf_rn(x2, q, 2.26843463243900e-03f);
    q = __fmaf_rn(x2, q, 4.89352518554385e-03f);
    float r = __fdiv_rn(p, q);
    return (ax < 0.0004f) ? x : r;
}

__device__ __forceinline__ float sigmoid_xla(float x) {
    float t = xla_tanhf(__fmul_rn(0.5f, x));
    return __fmaf_rn(0.5f, t, 0.5f);
}

// ---------------------------------------------------------------------------
// Kernel 1: decode (verbatim R13). CTA 0 zeroes tournament counters.
// ---------------------------------------------------------------------------
__global__ void decode_kernel(const float* __restrict__ in,
                              const float* __restrict__ anchors,
                              float* __restrict__ out) {
    __shared__ float s_out[256 * NATTR];

    if (blockIdx.x == 0 && threadIdx.x < BATCH * 8)
        ((int*)g_scnt)[threadIdx.x] = 0;

    int t = blockIdx.x * 256 + threadIdx.x;     // grid sized exactly: no tail
    int b = t / NBOX, n = t % NBOX;
    int a = n / HW,   r = n % HW;
    int gy = r / IW,  gx = r % IW;

    const float* base = in + ((size_t)(b * NA + a) * NATTR) * HW + r;
    float t0 = base[0 * HW];
    float t1 = base[1 * HW];
    float t2 = base[2 * HW];
    float t3 = base[3 * HW];
    float t4 = base[4 * HW];

    float aw = __fdiv_rn(anchors[a * 2 + 0], STRIDE_F);
    float ah = __fdiv_rn(anchors[a * 2 + 1], STRIDE_F);

    float sx = sigmoid_xla(t0);
    float sy = sigmoid_xla(t1);
    float bx = __fmul_rn(__fadd_rn(sx, (float)gx), STRIDE_F);
    float by = __fmul_rn(__fadd_rn(sy, (float)gy), STRIDE_F);
    float bw = __fmul_rn(__fmul_rn(__nv_expf(t2), aw), STRIDE_F);
    float bh = __fmul_rn(__fmul_rn(__nv_expf(t3), ah), STRIDE_F);
    float conf = sigmoid_xla(t4);

    float* so = s_out + threadIdx.x * NATTR;
    so[0] = bx; so[1] = by; so[2] = bw; so[3] = bh; so[4] = conf;

    float bestv = -3.402823466e+38f;
    int best = 0;
#pragma unroll
    for (int c = 0; c < NC; c++) {
        float v = sigmoid_xla(base[(5 + c) * HW]);
        so[5 + c] = v;
        if (v > bestv) { bestv = v; best = c; }
    }
    g_conf[b][n] = conf;
    g_cls[b][n]  = best;
    __syncthreads();

    float* oblk = out + (size_t)blockIdx.x * 256 * NATTR;
    for (int k = threadIdx.x; k < 256 * NATTR; k += 256)
        oblk[k] = s_out[k];
}

// ---------------------------------------------------------------------------
// Top-K machinery (verbatim R13).
// ---------------------------------------------------------------------------
__device__ __forceinline__ u64 cex(u64 a, u64 v, bool lower, bool desc) {
    u64 mx = a > v ? a : v;
    u64 mn = a > v ? v : a;
    return desc ? (lower ? mx : mn) : (lower ? mn : mx);
}

__device__ __forceinline__ void bitonic_merge_2048(u64& r0, u64& r1,
                                                   u64* s, int t, bool dirDesc) {
    {   // j = 1024: in-thread pair, r0 is lower
        bool sw = dirDesc ? (r0 < r1) : (r0 > r1);
        if (sw) { u64 tmp = r0; r0 = r1; r1 = tmp; }
    }
#pragma unroll
    for (int j = 512; j >= 32; j >>= 1) {
        s[t] = r0; s[t + 1024] = r1;
        __syncthreads();
        u64 v0 = s[t ^ j];
        u64 v1 = s[(t ^ j) + 1024];
        bool lower = (t & j) == 0;
        r0 = cex(r0, v0, lower, dirDesc);
        r1 = cex(r1, v1, lower, dirDesc);
        __syncthreads();
    }
#pragma unroll
    for (int j = 16; j >= 1; j >>= 1) {
        u64 v0 = __shfl_xor_sync(0xFFFFFFFFu, r0, j);
        u64 v1 = __shfl_xor_sync(0xFFFFFFFFu, r1, j);
        bool lower = (t & j) == 0;
        r0 = cex(r0, v0, lower, dirDesc);
        r1 = cex(r1, v1, lower, dirDesc);
    }
}

// Fused tournament sort (verbatim R13).
__global__ void sort_fused(const float* __restrict__ out,
                           float* __restrict__ out_topidx) {
    __shared__ u64 s[2048];
    __shared__ int s_go;
    __shared__ unsigned s_vab32[64];
    int c = blockIdx.x, b = blockIdx.y, t = threadIdx.x;

    // ---- phase 1: local sort of run c ----
    {
        int i = c * 1024 + t;
        u64 mine = 0ull;
        if (i < NBOX) {
            unsigned cb = __float_as_uint(g_conf[b][i]);
            mine = ((u64)cb << 32) | (unsigned)(0xFFFFFFFFu - (unsigned)i);
        }
        bool dirDesc = ((__popc(c) & 1) == 0);

        for (int k2 = 2; k2 <= 1024; k2 <<= 1) {
            for (int j = k2 >> 1; j > 0; j >>= 1) {
                bool descb = (((t & k2) == 0) == dirDesc);
                bool lower = (t & j) == 0;
                if (j >= 32) {
                    s[t] = mine;
                    __syncthreads();
                    u64 v = s[t ^ j];
                    mine = cex(mine, v, lower, descb);
                    __syncthreads();
                } else {
                    u64 v = __shfl_xor_sync(0xFFFFFFFFu, mine, j);
                    mine = cex(mine, v, lower, descb);
                }
            }
        }
        g_runA[b][c * 1024 + t] = mine;
    }
    __threadfence();
    __syncthreads();

    // ---- continuation 1: pair merge ----
    int pc = c >> 1;
    if (t == 0) s_go = atomicAdd(&g_scnt[b][pc], 1);
    __syncthreads();
    if (s_go == 0) return;
    __threadfence();
    {
        const u64* A  = g_runA[b] + 2 * pc * 1024;
        const u64* Bp = A + 1024;
        bool dirDesc = ((__popc(pc) & 1) == 0);
        u64 r0 = A[t];
        u64 r1 = Bp[t];
        bitonic_merge_2048(r0, r1, s, t, dirDesc);
        g_runB[b][pc * 2048 + t]        = r0;
        g_runB[b][pc * 2048 + 1024 + t] = r1;
    }
    __threadfence();
    __syncthreads();

    // ---- continuation 2: quad truncating merge ----
    int qc = pc >> 1;
    if (t == 0) s_go = atomicAdd(&g_scnt[b][4 + qc], 1);
    __syncthreads();
    if (s_go == 0) return;
    __threadfence();
    {
        const u64* A  = g_runB[b] + 2 * qc * 2048;
        const u64* Bp = A + 2048;
        bool dirDesc = ((__popc(qc) & 1) == 0);
        u64 a0 = A[t],        b0 = Bp[t];
        u64 a1 = A[t + 1024], b1 = Bp[t + 1024];
        u64 r0 = a0 > b0 ? a0 : b0;    // bitonic split: top half
        u64 r1 = a1 > b1 ? a1 : b1;
        bitonic_merge_2048(r0, r1, s, t, dirDesc);
        g_runA[b][qc * 2048 + t]        = r0;
        g_runA[b][qc * 2048 + 1024 + t] = r1;
    }
    __threadfence();
    __syncthreads();

    // ---- continuation 3: final truncating merge + prep ----
    if (t == 0) s_go = atomicAdd(&g_scnt[b][6], 1);
    __syncthreads();
    if (s_go == 0) return;
    __threadfence();

    if (t < 64) s_vab32[t] = 0u;
    u64 fr0, fr1;
    {
        const u64* A  = g_runA[b];
        const u64* Bp = A + 2048;
        u64 a0 = A[t],        b0 = Bp[t];
        u64 a1 = A[t + 1024], b1 = Bp[t + 1024];
        fr0 = a0 > b0 ? a0 : b0;
        fr1 = a1 > b1 ? a1 : b1;
        bitonic_merge_2048(fr0, fr1, s, t, true);
    }

#pragma unroll
    for (int q = 0; q < 2; q++) {
        int i = t + q * 1024;
        u64 kk = q ? fr1 : fr0;
        int n = (int)(0xFFFFFFFFu - (unsigned)(kk & 0xFFFFFFFFull));
        out_topidx[b * TOPK + i] = (float)n;
        g_rnz[b][i] = 0u;

        const float* o = out + ((size_t)b * NBOX + n) * NATTR;
        float cx = o[0], cy = o[1], w = o[2], h = o[3];
        float conf = __uint_as_float((unsigned)(kk >> 32));
        float hw2 = __fmul_rn(w, 0.5f);
        float hh2 = __fmul_rn(h, 0.5f);
        float x1 = __fsub_rn(cx, hw2);
        float y1 = __fsub_rn(cy, hh2);
        float x2 = __fadd_rn(cx, hw2);
        float y2 = __fadd_rn(cy, hh2);
        g_x1[b][i] = x1; g_y1[b][i] = y1; g_x2[b][i] = x2; g_y2[b][i] = y2;
        g_ar[b][i] = __fmul_rn(__fadd_rn(__fsub_rn(x2, x1), 1.0f),
                               __fadd_rn(__fsub_rn(y2, y1), 1.0f));
        g_cl[b][i] = (short)g_cls[b][n];
        if (conf >= 0.5f)
            atomicOr(&s_vab32[i >> 5], 1u << (i & 31));
    }
    __syncthreads();
    if (t < 64) ((unsigned*)g_vab[b])[t] = s_vab32[t];
}

// ---------------------------------------------------------------------------
// Kernel 3: suppression mask (verbatim R13 sparse version).
// ---------------------------------------------------------------------------
__global__ void nms_mask(void) {
    int jb = blockIdx.x, ib = blockIdx.y, b = blockIdx.z;
    if (jb < ib) return;

    __shared__ float jx1[64], jy1[64], jx2[64], jy2[64], jar[64];
    __shared__ u64 s_cm[NC];

    int t = threadIdx.x;
    int j0 = jb * 64;
    if (t < NC) s_cm[t] = 0ull;
    __syncthreads();
    jx1[t] = g_x1[b][j0 + t];
    jy1[t] = g_y1[b][j0 + t];
    jx2[t] = g_x2[b][j0 + t];
    jy2[t] = g_y2[b][j0 + t];
    jar[t] = g_ar[b][j0 + t];
    atomicOr(&s_cm[g_cl[b][j0 + t]], 1ull << t);
    __syncthreads();

    int i = ib * 64 + t;
    float xi1 = g_x1[b][i], yi1 = g_y1[b][i];
    float xi2 = g_x2[b][i], yi2 = g_y2[b][i];
    float ai  = g_ar[b][i];
    short ci  = g_cl[b][i];

    u64 mm = s_cm[ci];
    if (jb == ib) mm = (t < 63) ? (mm & (~0ull << (t + 1))) : 0ull;

    u64 bits = 0ull;
    while (mm) {
        int jj = __ffsll((long long)mm) - 1;
        mm &= mm - 1;
        float ix1 = fmaxf(xi1, jx1[jj]);
        float iy1 = fmaxf(yi1, jy1[jj]);
        float ix2 = fminf(xi2, jx2[jj]);
        float iy2 = fminf(yi2, jy2[jj]);
        float iw = __fadd_rn(__fsub_rn(ix2, ix1), 1.0f); iw = fmaxf(iw, 0.0f);
        float ih = __fadd_rn(__fsub_rn(iy2, iy1), 1.0f); ih = fmaxf(ih, 0.0f);
        float inter = __fmul_rn(iw, ih);
        float den = __fadd_rn(__fsub_rn(__fadd_rn(ai, jar[jj]), inter), 1e-16f);
        float iou = __fdiv_rn(inter, den);
        if (iou >= 0.4f) bits |= 1ull << jj;
    }
    if (jb == ib) {
        g_mask[b][i][jb] = bits;            // diagonal always valid
    } else if (bits) {
        g_mask[b][i][jb] = bits;
        atomicOr(&g_rnz[b][i], 1u << jb);
    }
}

// ---------------------------------------------------------------------------
// Kernel 4: edge-list greedy reduce. Blocks with no incoming suppression
// edges resolve in PARALLEL; only edge-receiving blocks serialize (t0,
// barrier-free, all smem). Fallback to the R12 serial loop if edges > MAXE.
// ---------------------------------------------------------------------------
__global__ void nms_reduce(float* __restrict__ keep_out) {
    __shared__ u64 diagAll[NBLK][64];       // 16 KB
    __shared__ unsigned s_rnz[TOPK];        // 8 KB
    __shared__ u64 edge_val[MAXE];          // 16 KB
    __shared__ short edge_row[MAXE];        // 4 KB
    __shared__ int cnt[NWORDS], basei[NWORDS], fill[NWORDS];
    __shared__ u64 s_vab[NWORDS], keepA[NBLK], s_act[NBLK], s_offnz[NBLK];
    __shared__ int s_total;

    int b = blockIdx.x, t = threadIdx.x;    // 256 threads
    if (t < NWORDS) {
        s_vab[t] = g_vab[b][t];
        cnt[t] = 0; fill[t] = 0;
        s_act[t] = 0ull; s_offnz[t] = 0ull;
    }
    __syncthreads();

    // preload diagonals + rnz; count incoming edges per word; act/offnz masks
    for (int k = t; k < TOPK; k += 256) {
        int bk = k >> 6, u = k & 63;
        u64 d = g_mask[b][k][bk];
        diagAll[bk][u] = d;
        if (d) atomicOr(&s_act[bk], 1ull << u);
        unsigned rz = g_rnz[b][k];
        s_rnz[k] = rz;
        if (rz) atomicOr(&s_offnz[bk], 1ull << u);
        while (rz) { int w = __ffs(rz) - 1; rz &= rz - 1; atomicAdd(&cnt[w], 1); }
    }
    __syncthreads();

    if (t == 0) {
        int acc = 0;
        for (int w = 0; w < NWORDS; w++) { basei[w] = acc; acc += cnt[w]; }
        s_total = acc;
    }
    __syncthreads();
    int total = s_total;

    if (total <= MAXE) {
        // gather edge words in parallel (independent L2 loads)
        for (int k = t; k < TOPK; k += 256) {
            unsigned rz = s_rnz[k];
            while (rz) {
                int w = __ffs(rz) - 1; rz &= rz - 1;
                int p = basei[w] + atomicAdd(&fill[w], 1);
                edge_row[p] = (short)k;
                edge_val[p] = g_mask[b][k][w];
            }
        }
        __syncthreads();

        // Phase A: parallel resolve of blocks with NO incoming edges (rem=0)
        if (t < NWORDS && cnt[t] == 0) {
            u64 cand = s_vab[t];
            u64 act = cand & s_act[t];
            while (act) {
                int u = __ffsll((long long)act) - 1;
                u64 d = diagAll[t][u];
                act &= ~(1ull << u);
                cand &= ~d;
                act &= ~d;
            }
            keepA[t] = cand;
        }
        __syncthreads();

        // Phase B: serial resolve of edge-receiving blocks (ascending);
        // senders are always lower-numbered blocks, hence already resolved.
        if (t == 0) {
            for (int w = 0; w < NWORDS; w++) {
                if (cnt[w] == 0) continue;
                u64 rem = 0ull;
                int e0 = basei[w], e1 = e0 + cnt[w];
                for (int e = e0; e < e1; e++) {
                    int r = edge_row[e];
                    if ((keepA[r >> 6] >> (r & 63)) & 1ull)
                        rem |= edge_val[e];
                }
                u64 cand = s_vab[w] & ~rem;
                u64 act = cand & s_act[w];
                while (act) {
                    int u = __ffsll((long long)act) - 1;
                    u64 d = diagAll[w][u];
                    act &= ~(1ull << u);
                    cand &= ~d;
                    act &= ~d;
                }
                keepA[w] = cand;
            }
        }
        __syncthreads();
    } else {
        // Fallback: R12 serial loop (verbatim semantics)
        __shared__ u64 s_rem[NWORDS];
        __shared__ u64 s_keep;
        if (t < NWORDS) s_rem[t] = 0ull;
        __syncthreads();
        for (int bk = 0; bk < NBLK; bk++) {
            if (t == 0) {
                u64 cand = s_vab[bk] & ~s_rem[bk];
                u64 act = cand & s_act[bk];
                while (act) {
                    int u = __ffsll((long long)act) - 1;
                    u64 d = diagAll[bk][u];
                    act &= ~(1ull << u);
                    cand &= ~d;
                    act &= ~d;
                }
                s_keep = cand;
            }
            __syncthreads();
            u64 k64 = s_keep;
            if (t == 0) keepA[bk] = k64;
            if (t < NWORDS) {
                int w = t;
                u64 ka = k64 & s_offnz[bk];
                if (w > bk && ka) {
                    u64 part = 0ull;
                    while (ka) {
                        int u = __ffsll((long long)ka) - 1;
                        ka &= ka - 1;
                        int row = bk * 64 + u;
                        if ((s_rnz[row] >> w) & 1u)
                            part |= g_mask[b][row][w];
                    }
                    if (part) atomicOr(&s_rem[w], part);
                }
            }
            __syncthreads();
        }
    }

    // write keep
    for (int k = t; k < TOPK; k += 256)
        keep_out[b * TOPK + k] =
            ((keepA[k >> 6] >> (k & 63)) & 1ull) ? 1.0f : 0.0f;
}

// ---------------------------------------------------------------------------
// Launch: out = [output(B*NBOX*NATTR) | top_idx(B*TOPK) | keep(B*TOPK)] float32
// ---------------------------------------------------------------------------
extern "C" void kernel_launch(void* const* d_in, const int* in_sizes, int n_in,
                              void* d_out, int out_size) {
    (void)in_sizes; (void)n_in; (void)out_size;
    const float* in      = (const float*)d_in[0];
    const float* anchors = (const float*)d_in[1];
    float* out      = (float*)d_out;
    float* top_out  = out + (size_t)BATCH * NBOX * NATTR;
    float* keep_out = top_out + (size_t)BATCH * TOPK;

    int total = BATCH * NBOX;                 // 129792 = 256 * 507, no tail
    decode_kernel<<<total / 256, 256>>>(in, anchors, out);

    sort_fused<<<dim3(8, BATCH), 1024>>>(out, top_out);

    nms_mask<<<dim3(TOPK / 64, TOPK / 64, BATCH), 64>>>();
    nms_reduce<<<BATCH, 256>>>(keep_out);
}

// round 15
// speedup vs baseline: 2.8624x; 1.1631x over previous
#include <cuda_runtime.h>
#include <cstdint>

// Problem constants
#define BATCH 16
#define NA    3
#define NC    20
#define NATTR 25          // 5 + NC
#define IH    52
#define IW    52
#define HW    2704        // IH*IW
#define NBOX  8112        // NA*HW
#define NPAD  8192
#define TOPK  2048
#define NWORDS (TOPK / 64)    // 32 u64 words per suppression row
#define NBLK   (TOPK / 64)    // 32 blocks of 64 candidates
#define MAXE  2048            // edge-list capacity (fallback if exceeded)
#define STRIDE_F 8.0f

typedef unsigned long long u64;

// Accurate libdevice expf (XLA's f32 exp lowering), immune to --use_fast_math.
extern "C" __device__ float __nv_expf(float);

// Scratch (allocation-free: __device__ globals)
__device__ float g_conf[BATCH][NBOX];
__device__ int   g_cls [BATCH][NBOX];
__device__ u64   g_runA[BATCH][NPAD];
__device__ u64   g_runB[BATCH][NPAD];
__device__ int   g_scnt[BATCH][8];              // tournament counters

// NMS staging
__device__ float g_x1[BATCH][TOPK];
__device__ float g_y1[BATCH][TOPK];
__device__ float g_x2[BATCH][TOPK];
__device__ float g_y2[BATCH][TOPK];
__device__ float g_ar[BATCH][TOPK];
__device__ short g_cl[BATCH][TOPK];
__device__ u64   g_vab[BATCH][NWORDS];          // validity bitmask
__device__ u64   g_mask[BATCH][TOPK][NWORDS];   // suppression matrix (sparse-written)
__device__ unsigned g_rnz[BATCH][TOPK];         // per-row nonzero-word bitmask

// ---------------------------------------------------------------------------
// Bitwise replica of XLA:GPU's tanh (llvm_ir::EmitFastTanh).
// ---------------------------------------------------------------------------
__device__ __forceinline__ float xla_tanhf(float x) {
    float ax = fabsf(x);
    float xc = fminf(fmaxf(x, -7.90531110763549805f), 7.90531110763549805f);
    float x2 = __fmul_rn(xc, xc);
    float p = -2.76076847742355e-16f;
    p = __fmaf_rn(x2, p, 2.00018790482477e-13f);
    p = __fmaf_rn(x2, p, -8.60467152213735e-11f);
    p = __fmaf_rn(x2, p, 5.12229709037114e-08f);
    p = __fmaf_rn(x2, p, 1.48572235717979e-05f);
    p = __fmaf_rn(x2, p, 6.37261928875436e-04f);
    p = __fmaf_rn(x2, p, 4.89352455891786e-03f);
    p = __fmul_rn(xc, p);
    float q = 1.19825839466702e-06f;
    q = __fmaf_rn(x2, q, 1.18534705686654e-04f);
    q = __fmaf_rn(x2, q, 2.26843463243900e-03f);
    q = __fmaf_rn(x2, q, 4.89352518554385e-03f);
    float r = __fdiv_rn(p, q);
    return (ax < 0.0004f) ? x : r;
}

__device__ __forceinline__ float sigmoid_xla(float x) {
    float t = xla_tanhf(__fmul_rn(0.5f, x));
    return __fmaf_rn(0.5f, t, 0.5f);
}

// ---------------------------------------------------------------------------
// Kernel 1: decode (verbatim R14). CTA 0 zeroes tournament counters.
// ---------------------------------------------------------------------------
__global__ void decode_kernel(const float* __restrict__ in,
                              const float* __restrict__ anchors,
                              float* __restrict__ out) {
    __shared__ float s_out[256 * NATTR];

    if (blockIdx.x == 0 && threadIdx.x < BATCH * 8)
        ((int*)g_scnt)[threadIdx.x] = 0;

    int t = blockIdx.x * 256 + threadIdx.x;     // grid sized exactly: no tail
    int b = t / NBOX, n = t % NBOX;
    int a = n / HW,   r = n % HW;
    int gy = r / IW,  gx = r % IW;

    const float* base = in + ((size_t)(b * NA + a) * NATTR) * HW + r;
    float t0 = base[0 * HW];
    float t1 = base[1 * HW];
    float t2 = base[2 * HW];
    float t3 = base[3 * HW];
    float t4 = base[4 * HW];

    float aw = __fdiv_rn(anchors[a * 2 + 0], STRIDE_F);
    float ah = __fdiv_rn(anchors[a * 2 + 1], STRIDE_F);

    float sx = sigmoid_xla(t0);
    float sy = sigmoid_xla(t1);
    float bx = __fmul_rn(__fadd_rn(sx, (float)gx), STRIDE_F);
    float by = __fmul_rn(__fadd_rn(sy, (float)gy), STRIDE_F);
    float bw = __fmul_rn(__fmul_rn(__nv_expf(t2), aw), STRIDE_F);
    float bh = __fmul_rn(__fmul_rn(__nv_expf(t3), ah), STRIDE_F);
    float conf = sigmoid_xla(t4);

    float* so = s_out + threadIdx.x * NATTR;
    so[0] = bx; so[1] = by; so[2] = bw; so[3] = bh; so[4] = conf;

    float bestv = -3.402823466e+38f;
    int best = 0;
#pragma unroll
    for (int c = 0; c < NC; c++) {
        float v = sigmoid_xla(base[(5 + c) * HW]);
        so[5 + c] = v;
        if (v > bestv) { bestv = v; best = c; }
    }
    g_conf[b][n] = conf;
    g_cls[b][n]  = best;
    __syncthreads();

    float* oblk = out + (size_t)blockIdx.x * 256 * NATTR;
    for (int k = threadIdx.x; k < 256 * NATTR; k += 256)
        oblk[k] = s_out[k];
}

// ---------------------------------------------------------------------------
// Top-K machinery (verbatim R14).
// ---------------------------------------------------------------------------
__device__ __forceinline__ u64 cex(u64 a, u64 v, bool lower, bool desc) {
    u64 mx = a > v ? a : v;
    u64 mn = a > v ? v : a;
    return desc ? (lower ? mx : mn) : (lower ? mn : mx);
}

__device__ __forceinline__ void bitonic_merge_2048(u64& r0, u64& r1,
                                                   u64* s, int t, bool dirDesc) {
    {   // j = 1024: in-thread pair, r0 is lower
        bool sw = dirDesc ? (r0 < r1) : (r0 > r1);
        if (sw) { u64 tmp = r0; r0 = r1; r1 = tmp; }
    }
#pragma unroll
    for (int j = 512; j >= 32; j >>= 1) {
        s[t] = r0; s[t + 1024] = r1;
        __syncthreads();
        u64 v0 = s[t ^ j];
        u64 v1 = s[(t ^ j) + 1024];
        bool lower = (t & j) == 0;
        r0 = cex(r0, v0, lower, dirDesc);
        r1 = cex(r1, v1, lower, dirDesc);
        __syncthreads();
    }
#pragma unroll
    for (int j = 16; j >= 1; j >>= 1) {
        u64 v0 = __shfl_xor_sync(0xFFFFFFFFu, r0, j);
        u64 v1 = __shfl_xor_sync(0xFFFFFFFFu, r1, j);
        bool lower = (t & j) == 0;
        r0 = cex(r0, v0, lower, dirDesc);
        r1 = cex(r1, v1, lower, dirDesc);
    }
}

// Fused tournament sort (verbatim R14).
__global__ void sort_fused(const float* __restrict__ out,
                           float* __restrict__ out_topidx) {
    __shared__ u64 s[2048];
    __shared__ int s_go;
    __shared__ unsigned s_vab32[64];
    int c = blockIdx.x, b = blockIdx.y, t = threadIdx.x;

    // ---- phase 1: local sort of run c ----
    {
        int i = c * 1024 + t;
        u64 mine = 0ull;
        if (i < NBOX) {
            unsigned cb = __float_as_uint(g_conf[b][i]);
            mine = ((u64)cb << 32) | (unsigned)(0xFFFFFFFFu - (unsigned)i);
        }
        bool dirDesc = ((__popc(c) & 1) == 0);

        for (int k2 = 2; k2 <= 1024; k2 <<= 1) {
            for (int j = k2 >> 1; j > 0; j >>= 1) {
                bool descb = (((t & k2) == 0) == dirDesc);
                bool lower = (t & j) == 0;
                if (j >= 32) {
                    s[t] = mine;
                    __syncthreads();
                    u64 v = s[t ^ j];
                    mine = cex(mine, v, lower, descb);
                    __syncthreads();
                } else {
                    u64 v = __shfl_xor_sync(0xFFFFFFFFu, mine, j);
                    mine = cex(mine, v, lower, descb);
                }
            }
        }
        g_runA[b][c * 1024 + t] = mine;
    }
    __threadfence();
    __syncthreads();

    // ---- continuation 1: pair merge ----
    int pc = c >> 1;
    if (t == 0) s_go = atomicAdd(&g_scnt[b][pc], 1);
    __syncthreads();
    if (s_go == 0) return;
    __threadfence();
    {
        const u64* A  = g_runA[b] + 2 * pc * 1024;
        const u64* Bp = A + 1024;
        bool dirDesc = ((__popc(pc) & 1) == 0);
        u64 r0 = A[t];
        u64 r1 = Bp[t];
        bitonic_merge_2048(r0, r1, s, t, dirDesc);
        g_runB[b][pc * 2048 + t]        = r0;
        g_runB[b][pc * 2048 + 1024 + t] = r1;
    }
    __threadfence();
    __syncthreads();

    // ---- continuation 2: quad truncating merge ----
    int qc = pc >> 1;
    if (t == 0) s_go = atomicAdd(&g_scnt[b][4 + qc], 1);
    __syncthreads();
    if (s_go == 0) return;
    __threadfence();
    {
        const u64* A  = g_runB[b] + 2 * qc * 2048;
        const u64* Bp = A + 2048;
        bool dirDesc = ((__popc(qc) & 1) == 0);
        u64 a0 = A[t],        b0 = Bp[t];
        u64 a1 = A[t + 1024], b1 = Bp[t + 1024];
        u64 r0 = a0 > b0 ? a0 : b0;    // bitonic split: top half
        u64 r1 = a1 > b1 ? a1 : b1;
        bitonic_merge_2048(r0, r1, s, t, dirDesc);
        g_runA[b][qc * 2048 + t]        = r0;
        g_runA[b][qc * 2048 + 1024 + t] = r1;
    }
    __threadfence();
    __syncthreads();

    // ---- continuation 3: final truncating merge + prep ----
    if (t == 0) s_go = atomicAdd(&g_scnt[b][6], 1);
    __syncthreads();
    if (s_go == 0) return;
    __threadfence();

    if (t < 64) s_vab32[t] = 0u;
    u64 fr0, fr1;
    {
        const u64* A  = g_runA[b];
        const u64* Bp = A + 2048;
        u64 a0 = A[t],        b0 = Bp[t];
        u64 a1 = A[t + 1024], b1 = Bp[t + 1024];
        fr0 = a0 > b0 ? a0 : b0;
        fr1 = a1 > b1 ? a1 : b1;
        bitonic_merge_2048(fr0, fr1, s, t, true);
    }

#pragma unroll
    for (int q = 0; q < 2; q++) {
        int i = t + q * 1024;
        u64 kk = q ? fr1 : fr0;
        int n = (int)(0xFFFFFFFFu - (unsigned)(kk & 0xFFFFFFFFull));
        out_topidx[b * TOPK + i] = (float)n;
        g_rnz[b][i] = 0u;

        const float* o = out + ((size_t)b * NBOX + n) * NATTR;
        float cx = o[0], cy = o[1], w = o[2], h = o[3];
        float conf = __uint_as_float((unsigned)(kk >> 32));
        float hw2 = __fmul_rn(w, 0.5f);
        float hh2 = __fmul_rn(h, 0.5f);
        float x1 = __fsub_rn(cx, hw2);
        float y1 = __fsub_rn(cy, hh2);
        float x2 = __fadd_rn(cx, hw2);
        float y2 = __fadd_rn(cy, hh2);
        g_x1[b][i] = x1; g_y1[b][i] = y1; g_x2[b][i] = x2; g_y2[b][i] = y2;
        g_ar[b][i] = __fmul_rn(__fadd_rn(__fsub_rn(x2, x1), 1.0f),
                               __fadd_rn(__fsub_rn(y2, y1), 1.0f));
        g_cl[b][i] = (short)g_cls[b][n];
        if (conf >= 0.5f)
            atomicOr(&s_vab32[i >> 5], 1u << (i & 31));
    }
    __syncthreads();
    if (t < 64) ((unsigned*)g_vab[b])[t] = s_vab32[t];
}

// ---------------------------------------------------------------------------
// Kernel 3: suppression mask (verbatim R14 sparse version).
// ---------------------------------------------------------------------------
__global__ void nms_mask(void) {
    int jb = blockIdx.x, ib = blockIdx.y, b = blockIdx.z;
    if (jb < ib) return;

    __shared__ float jx1[64], jy1[64], jx2[64], jy2[64], jar[64];
    __shared__ u64 s_cm[NC];

    int t = threadIdx.x;
    int j0 = jb * 64;
    if (t < NC) s_cm[t] = 0ull;
    __syncthreads();
    jx1[t] = g_x1[b][j0 + t];
    jy1[t] = g_y1[b][j0 + t];
    jx2[t] = g_x2[b][j0 + t];
    jy2[t] = g_y2[b][j0 + t];
    jar[t] = g_ar[b][j0 + t];
    atomicOr(&s_cm[g_cl[b][j0 + t]], 1ull << t);
    __syncthreads();

    int i = ib * 64 + t;
    float xi1 = g_x1[b][i], yi1 = g_y1[b][i];
    float xi2 = g_x2[b][i], yi2 = g_y2[b][i];
    float ai  = g_ar[b][i];
    short ci  = g_cl[b][i];

    u64 mm = s_cm[ci];
    if (jb == ib) mm = (t < 63) ? (mm & (~0ull << (t + 1))) : 0ull;

    u64 bits = 0ull;
    while (mm) {
        int jj = __ffsll((long long)mm) - 1;
        mm &= mm - 1;
        float ix1 = fmaxf(xi1, jx1[jj]);
        float iy1 = fmaxf(yi1, jy1[jj]);
        float ix2 = fminf(xi2, jx2[jj]);
        float iy2 = fminf(yi2, jy2[jj]);
        float iw = __fadd_rn(__fsub_rn(ix2, ix1), 1.0f); iw = fmaxf(iw, 0.0f);
        float ih = __fadd_rn(__fsub_rn(iy2, iy1), 1.0f); ih = fmaxf(ih, 0.0f);
        float inter = __fmul_rn(iw, ih);
        float den = __fadd_rn(__fsub_rn(__fadd_rn(ai, jar[jj]), inter), 1e-16f);
        float iou = __fdiv_rn(inter, den);
        if (iou >= 0.4f) bits |= 1ull << jj;
    }
    if (jb == ib) {
        g_mask[b][i][jb] = bits;            // diagonal always valid
    } else if (bits) {
        g_mask[b][i][jb] = bits;
        atomicOr(&g_rnz[b][i], 1u << jb);
    }
}

// ---------------------------------------------------------------------------
// Kernel 4: edge-list greedy reduce (R14) with WARP-PARALLEL Phase B: warp 0
// stripes each block's edge list across 32 lanes, OR-reduces with
// __reduce_or_sync, lane 0 runs the validated resolve chain. Ascending block
// order preserved (senders always in lower words).
// ---------------------------------------------------------------------------
__global__ void nms_reduce(float* __restrict__ keep_out) {
    __shared__ u64 diagAll[NBLK][64];       // 16 KB
    __shared__ unsigned s_rnz[TOPK];        // 8 KB
    __shared__ u64 edge_val[MAXE];          // 16 KB
    __shared__ short edge_row[MAXE];        // 4 KB
    __shared__ int cnt[NWORDS], basei[NWORDS], fill[NWORDS];
    __shared__ u64 s_vab[NWORDS], keepA[NBLK], s_act[NBLK], s_offnz[NBLK];
    __shared__ int s_total;

    int b = blockIdx.x, t = threadIdx.x;    // 256 threads
    if (t < NWORDS) {
        s_vab[t] = g_vab[b][t];
        cnt[t] = 0; fill[t] = 0;
        s_act[t] = 0ull; s_offnz[t] = 0ull;
    }
    __syncthreads();

    // preload diagonals + rnz; count incoming edges per word; act/offnz masks
    for (int k = t; k < TOPK; k += 256) {
        int bk = k >> 6, u = k & 63;
        u64 d = g_mask[b][k][bk];
        diagAll[bk][u] = d;
        if (d) atomicOr(&s_act[bk], 1ull << u);
        unsigned rz = g_rnz[b][k];
        s_rnz[k] = rz;
        if (rz) atomicOr(&s_offnz[bk], 1ull << u);
        while (rz) { int w = __ffs(rz) - 1; rz &= rz - 1; atomicAdd(&cnt[w], 1); }
    }
    __syncthreads();

    if (t == 0) {
        int acc = 0;
        for (int w = 0; w < NWORDS; w++) { basei[w] = acc; acc += cnt[w]; }
        s_total = acc;
    }
    __syncthreads();
    int total = s_total;

    if (total <= MAXE) {
        // gather edge words in parallel (independent L2 loads)
        for (int k = t; k < TOPK; k += 256) {
            unsigned rz = s_rnz[k];
            while (rz) {
                int w = __ffs(rz) - 1; rz &= rz - 1;
                int p = basei[w] + atomicAdd(&fill[w], 1);
                edge_row[p] = (short)k;
                edge_val[p] = g_mask[b][k][w];
            }
        }
        __syncthreads();

        // Phase A: parallel resolve of blocks with NO incoming edges (rem=0)
        if (t < NWORDS && cnt[t] == 0) {
            u64 cand = s_vab[t];
            u64 act = cand & s_act[t];
            while (act) {
                int u = __ffsll((long long)act) - 1;
                u64 d = diagAll[t][u];
                act &= ~(1ull << u);
                cand &= ~d;
                act &= ~d;
            }
            keepA[t] = cand;
        }
        __syncthreads();

        // Phase B: warp 0 resolves edge-receiving blocks ascending. Edge scan
        // striped across 32 lanes + OR-reduction; lane 0 resolves. Senders
        // are always lower-numbered blocks: written by Phase A (synced above)
        // or earlier Phase B iterations (__syncwarp below).
        if (t < 32) {
            int lane = t;
            for (int w = 0; w < NWORDS; w++) {
                if (cnt[w] == 0) continue;
                int e0 = basei[w], e1 = e0 + cnt[w];
                unsigned lo = 0u, hi = 0u;
                for (int e = e0 + lane; e < e1; e += 32) {
                    int r = edge_row[e];
                    if ((keepA[r >> 6] >> (r & 63)) & 1ull) {
                        u64 v = edge_val[e];
                        lo |= (unsigned)v;
                        hi |= (unsigned)(v >> 32);
                    }
                }
                lo = __reduce_or_sync(0xFFFFFFFFu, lo);
                hi = __reduce_or_sync(0xFFFFFFFFu, hi);
                if (lane == 0) {
                    u64 rem = ((u64)hi << 32) | lo;
                    u64 cand = s_vab[w] & ~rem;
                    u64 act = cand & s_act[w];
                    while (act) {
                        int u = __ffsll((long long)act) - 1;
                        u64 d = diagAll[w][u];
                        act &= ~(1ull << u);
                        cand &= ~d;
                        act &= ~d;
                    }
                    keepA[w] = cand;
                }
                __syncwarp();
            }
        }
        __syncthreads();
    } else {
        // Fallback: R12 serial loop (verbatim semantics)
        __shared__ u64 s_rem[NWORDS];
        __shared__ u64 s_keep;
        if (t < NWORDS) s_rem[t] = 0ull;
        __syncthreads();
        for (int bk = 0; bk < NBLK; bk++) {
            if (t == 0) {
                u64 cand = s_vab[bk] & ~s_rem[bk];
                u64 act = cand & s_act[bk];
                while (act) {
                    int u = __ffsll((long long)act) - 1;
                    u64 d = diagAll[bk][u];
                    act &= ~(1ull << u);
                    cand &= ~d;
                    act &= ~d;
                }
                s_keep = cand;
            }
            __syncthreads();
            u64 k64 = s_keep;
            if (t == 0) keepA[bk] = k64;
            if (t < NWORDS) {
                int w = t;
                u64 ka = k64 & s_offnz[bk];
                if (w > bk && ka) {
                    u64 part = 0ull;
                    while (ka) {
                        int u = __ffsll((long long)ka) - 1;
                        ka &= ka - 1;
                        int row = bk * 64 + u;
                        if ((s_rnz[row] >> w) & 1u)
                            part |= g_mask[b][row][w];
                    }
                    if (part) atomicOr(&s_rem[w], part);
                }
            }
            __syncthreads();
        }
    }

    // write keep
    for (int k = t; k < TOPK; k += 256)
        keep_out[b * TOPK + k] =
            ((keepA[k >> 6] >> (k & 63)) & 1ull) ? 1.0f : 0.0f;
}

// ---------------------------------------------------------------------------
// Launch: out = [output(B*NBOX*NATTR) | top_idx(B*TOPK) | keep(B*TOPK)] float32
// ---------------------------------------------------------------------------
extern "C" void kernel_launch(void* const* d_in, const int* in_sizes, int n_in,
                              void* d_out, int out_size) {
    (void)in_sizes; (void)n_in; (void)out_size;
    const float* in      = (const float*)d_in[0];
    const float* anchors = (const float*)d_in[1];
    float* out      = (float*)d_out;
    float* top_out  = out + (size_t)BATCH * NBOX * NATTR;
    float* keep_out = top_out + (size_t)BATCH * TOPK;

    int total = BATCH * NBOX;                 // 129792 = 256 * 507, no tail
    decode_kernel<<<total / 256, 256>>>(in, anchors, out);

    sort_fused<<<dim3(8, BATCH), 1024>>>(out, top_out);

    nms_mask<<<dim3(TOPK / 64, TOPK / 64, BATCH), 64>>>();
    nms_reduce<<<BATCH, 256>>>(keep_out);
}